// round 14
// baseline (speedup 1.0000x reference)
#include <cuda_runtime.h>
#include <cuda_bf16.h>
#include <cuda_fp16.h>
#include <math.h>
#include <stdint.h>

#define NNODE 20000
#define NEDGE 160000
#define NFEAT 512
#define NHID  256
#define NCLASS 64

// ---------------------------------------------------------------------------
// fp32 scratch offsets
// ---------------------------------------------------------------------------
#define OFF_NB1  0ll
#define OFF_TA1  (OFF_NB1 + (long long)NNODE*NFEAT)
#define OFF_TB1  (OFF_TA1 + (long long)NNODE*NFEAT)   // TA1+TB1 = fused T1 [N,1024]
#define OFF_H1   (OFF_TB1 + (long long)NNODE*NFEAT)
#define OFF_HS1  (OFF_H1  + (long long)NNODE*NHID)
#define OFF_X1   (OFF_HS1 + (long long)NNODE*NHID)
#define OFF_NB2  (OFF_X1  + (long long)NNODE*NHID)
#define OFF_TA2  (OFF_NB2 + (long long)NNODE*NHID)
#define OFF_TB2  (OFF_TA2 + (long long)NNODE*NHID)    // TA2+TB2 = fused T2 [N,512]
#define OFF_H2   (OFF_TB2 + (long long)NNODE*NHID)
#define OFF_HS2  (OFF_H2  + (long long)NNODE*NCLASS)
#define OFF_DINV (OFF_HS2 + (long long)NNODE*NCLASS)
#define SCRATCH_FLOATS (OFF_DINV + (long long)NNODE)

__device__ float g_scratch[SCRATCH_FLOATS];
__device__ int   g_ei32[2 * NEDGE];
__device__ unsigned g_idx_is32;
__device__ int   g_cnt[NNODE];
__device__ int   g_deg[NNODE];
__device__ int   g_rowptr[NNODE + 1];
__device__ int   g_colptr[NNODE + 1];
__device__ int   g_adj_row[NEDGE];
__device__ int   g_adj_col[NEDGE];
__device__ int   g_fill[2 * NNODE];

#define XPL   ((long long)NNODE*NFEAT)
#define X1PL  ((long long)NNODE*NHID)
// fp16 activation planes (rounded, single plane)
__device__ unsigned short g_xf16[XPL];
__device__ unsigned short g_nbf16[XPL];
__device__ unsigned short g_x1f16[X1PL];
// bf16 hi/lo activation planes (for gc GEMM A operands)
__device__ unsigned short g_xbh[XPL],  g_xbl[XPL];
__device__ unsigned short g_obh[XPL],  g_obl[XPL];
__device__ unsigned short g_x1bh[X1PL], g_x1bl[X1PL];
// fp16 hi/lo relation weight planes: [r1 g1;b1][r1 g2;b2][r2 g1;b1][r2 g2;b2]
#define W16_1A 0
#define W16_1B 524288
#define W16_2A 1048576
#define W16_2B 1179648
#define W16TOT 1310720
__device__ unsigned short g_w16h[W16TOT], g_w16l[W16TOT];
// bf16 hi/lo gc weight planes: gc1 @0 (131072), gc2 @131072 (16384)
#define WB_GC1 0
#define WB_GC2 131072
#define WBTOT  147456
__device__ unsigned short g_wbh[WBTOT], g_wbl[WBTOT];

typedef __nv_bfloat16 bf16;
typedef __nv_bfloat162 bf162;

// ---------------------------------------------------------------------------
// helpers
// ---------------------------------------------------------------------------
__device__ __forceinline__ void split2b(float x, float y, bf162* hp, bf162* lp)
{
    bf16 hx = __float2bfloat16(x);
    bf16 hy = __float2bfloat16(y);
    *hp = __halves2bfloat162(hx, hy);
    *lp = __halves2bfloat162(__float2bfloat16(x - __bfloat162float(hx)),
                             __float2bfloat16(y - __bfloat162float(hy)));
}

__device__ __forceinline__ void split2h(float x, float y, __half2* hp, __half2* lp)
{
    __half hx = __float2half_rn(x);
    __half hy = __float2half_rn(y);
    *hp = __halves2half2(hx, hy);
    *lp = __halves2half2(__float2half_rn(x - __half2float(hx)),
                         __float2half_rn(y - __half2float(hy)));
}

__device__ __forceinline__ void cpasync16(void* smem, const void* g, int sz)
{
    unsigned sa = (unsigned)__cvta_generic_to_shared(smem);
    asm volatile("cp.async.cg.shared.global [%0], [%1], 16, %2;\n"
                 :: "r"(sa), "l"(g), "r"(sz));
}
__device__ __forceinline__ void cp_commit()
{
    asm volatile("cp.async.commit_group;\n");
}

__device__ __forceinline__ void mma_bf(float* c, const uint32_t* a, const uint32_t* b)
{
    asm volatile(
        "mma.sync.aligned.m16n8k16.row.col.f32.bf16.bf16.f32 "
        "{%0,%1,%2,%3}, {%4,%5,%6,%7}, {%8,%9}, {%0,%1,%2,%3};\n"
        : "+f"(c[0]), "+f"(c[1]), "+f"(c[2]), "+f"(c[3])
        : "r"(a[0]), "r"(a[1]), "r"(a[2]), "r"(a[3]), "r"(b[0]), "r"(b[1]));
}

__device__ __forceinline__ void mma_h(float* c, const uint32_t* a, const uint32_t* b)
{
    asm volatile(
        "mma.sync.aligned.m16n8k16.row.col.f32.f16.f16.f32 "
        "{%0,%1,%2,%3}, {%4,%5,%6,%7}, {%8,%9}, {%0,%1,%2,%3};\n"
        : "+f"(c[0]), "+f"(c[1]), "+f"(c[2]), "+f"(c[3])
        : "r"(a[0]), "r"(a[1]), "r"(a[2]), "r"(a[3]), "r"(b[0]), "r"(b[1]));
}

template<typename T>
__device__ __forceinline__ uint32_t lds32(const T* s, int idx)
{
    return *reinterpret_cast<const uint32_t*>(&s[idx]);
}

// ---------------------------------------------------------------------------
// Edge-index canonicalization
// ---------------------------------------------------------------------------
__global__ void detect_idx(const int* __restrict__ raw)
{
    int i = blockIdx.x * blockDim.x + threadIdx.x;
    if (i < NEDGE) {
        if (raw[2 * i + 1] != 0) atomicOr(&g_idx_is32, 1u);
    }
}
__global__ void convert_idx(const int* __restrict__ raw)
{
    int i = blockIdx.x * blockDim.x + threadIdx.x;
    if (i < 2 * NEDGE) g_ei32[i] = g_idx_is32 ? raw[i] : raw[2 * i];
}

// ---------------------------------------------------------------------------
// CSR construction
// ---------------------------------------------------------------------------
__global__ void count_int(int E)
{
    int e = blockIdx.x * blockDim.x + threadIdx.x;
    if (e < E) {
        atomicAdd(&g_cnt[g_ei32[e]], 1);
        atomicAdd(&g_deg[g_ei32[E + e]], 1);
    }
}

__global__ __launch_bounds__(1024) void scan2()
{
    const int n = NNODE;
    const int CH = 20;
    const int* in  = blockIdx.x ? g_deg : g_cnt;
    int* out       = blockIdx.x ? g_colptr : g_rowptr;

    __shared__ int wsum[32];
    int tid = threadIdx.x, lane = tid & 31, wid = tid >> 5;
    int base = tid * CH;

    int vals[CH];
    int s = 0;
#pragma unroll
    for (int j = 0; j < CH; j++) {
        int v = (base + j < n) ? in[base + j] : 0;
        vals[j] = s;
        s += v;
    }
    int ws = s;
#pragma unroll
    for (int o = 1; o < 32; o <<= 1) {
        int t = __shfl_up_sync(0xFFFFFFFFu, ws, o);
        if (lane >= o) ws += t;
    }
    if (lane == 31) wsum[wid] = ws;
    __syncthreads();
    if (wid == 0) {
        int w = wsum[lane];
#pragma unroll
        for (int o = 1; o < 32; o <<= 1) {
            int t = __shfl_up_sync(0xFFFFFFFFu, w, o);
            if (lane >= o) w += t;
        }
        wsum[lane] = w;
    }
    __syncthreads();
    int off = (wid ? wsum[wid - 1] : 0) + ws - s;
#pragma unroll
    for (int j = 0; j < CH; j++) {
        if (base + j <= n) out[base + j] = off + vals[j];
    }
}

__global__ void fill_csr(int E)
{
    int e = blockIdx.x * blockDim.x + threadIdx.x;
    if (e < E) {
        int r = g_ei32[e];
        int c = g_ei32[E + e];
        int p = atomicAdd(&g_fill[r], 1);
        g_adj_row[g_rowptr[r] + p] = c;
        int q = atomicAdd(&g_fill[NNODE + c], 1);
        g_adj_col[g_colptr[c] + q] = r;
    }
}

__global__ void finalize_deg(float* __restrict__ dinv, int n)
{
    int i = blockIdx.x * blockDim.x + threadIdx.x;
    if (i < n) dinv[i] = rsqrtf((float)g_deg[i] + 1.f);
}

// ---------------------------------------------------------------------------
// split kernels
// ---------------------------------------------------------------------------
// x -> fp16 (rounded) + bf16 hi/lo
__global__ void splitx(const float* __restrict__ s,
                       unsigned short* __restrict__ f16,
                       unsigned short* __restrict__ bh,
                       unsigned short* __restrict__ bl, int n4)
{
    int i = blockIdx.x * blockDim.x + threadIdx.x;
    if (i >= n4) return;
    float4 v = reinterpret_cast<const float4*>(s)[i];
    __half2* fp = reinterpret_cast<__half2*>(f16) + (size_t)i * 2;
    fp[0] = __halves2half2(__float2half_rn(v.x), __float2half_rn(v.y));
    fp[1] = __halves2half2(__float2half_rn(v.z), __float2half_rn(v.w));
    bf162* hp = reinterpret_cast<bf162*>(bh) + (size_t)i * 2;
    bf162* lp = reinterpret_cast<bf162*>(bl) + (size_t)i * 2;
    split2b(v.x, v.y, hp, lp);
    split2b(v.z, v.w, hp + 1, lp + 1);
}

// up to 4 equal-size matrices -> fp16 hi/lo planes
__global__ void splitw16(const float* __restrict__ s0, const float* __restrict__ s1,
                         const float* __restrict__ s2, const float* __restrict__ s3,
                         unsigned short* __restrict__ h, unsigned short* __restrict__ l,
                         int n4)
{
    const float* s = (blockIdx.y == 0) ? s0 : (blockIdx.y == 1) ? s1
                   : (blockIdx.y == 2) ? s2 : s3;
    long long ob = (long long)blockIdx.y * n4;
    int i = blockIdx.x * blockDim.x + threadIdx.x;
    if (i >= n4) return;
    float4 v = reinterpret_cast<const float4*>(s)[i];
    __half2* hp = reinterpret_cast<__half2*>(h) + (ob + i) * 2;
    __half2* lp = reinterpret_cast<__half2*>(l) + (ob + i) * 2;
    split2h(v.x, v.y, hp, lp);
    split2h(v.z, v.w, hp + 1, lp + 1);
}

// single matrix -> bf16 hi/lo planes
__global__ void splitwb(const float* __restrict__ s,
                        unsigned short* __restrict__ h, unsigned short* __restrict__ l,
                        int n4)
{
    int i = blockIdx.x * blockDim.x + threadIdx.x;
    if (i >= n4) return;
    float4 v = reinterpret_cast<const float4*>(s)[i];
    bf162* hp = reinterpret_cast<bf162*>(h) + (size_t)i * 2;
    bf162* lp = reinterpret_cast<bf162*>(l) + (size_t)i * 2;
    split2b(v.x, v.y, hp, lp);
    split2b(v.z, v.w, hp + 1, lp + 1);
}

// ---------------------------------------------------------------------------
// Gather kernels (atomic-free)
// ---------------------------------------------------------------------------
template<int F>
__global__ __launch_bounds__(256)
void gather_mean(const float* __restrict__ x, float* __restrict__ nb,
                 unsigned short* __restrict__ nbf16)
{
    constexpr int L = F / 4;
    constexpr int NPB = 256 / L;
    int node = blockIdx.x * NPB + threadIdx.x / L;
    int lane = threadIdx.x % L;
    if (node >= NNODE) return;

    int beg = g_rowptr[node], end = g_rowptr[node + 1];
    float4 s = make_float4(0.f, 0.f, 0.f, 0.f);
    for (int p = beg; p < end; ++p) {
        int j = g_adj_row[p];
        float4 v = __ldg(reinterpret_cast<const float4*>(x + (size_t)j * F) + lane);
        s.x += v.x; s.y += v.y; s.z += v.z; s.w += v.w;
    }
    int c = end - beg;
    float inv = (c > 0) ? 1.f / (float)c : 0.f;
    s.x *= inv; s.y *= inv; s.z *= inv; s.w *= inv;
    size_t q = (size_t)node * L + lane;
    reinterpret_cast<float4*>(nb)[q] = s;
    __half2* fp = reinterpret_cast<__half2*>(nbf16) + q * 2;
    fp[0] = __halves2half2(__float2half_rn(s.x), __float2half_rn(s.y));
    fp[1] = __halves2half2(__float2half_rn(s.z), __float2half_rn(s.w));
}

template<int F, bool ELU>
__global__ __launch_bounds__(256)
void gcn_fused(const float* __restrict__ h, const float* __restrict__ hs,
               const float* __restrict__ bias, const float* __restrict__ dinv,
               float* __restrict__ out,
               unsigned short* __restrict__ f16o,
               unsigned short* __restrict__ pbh, unsigned short* __restrict__ pbl)
{
    constexpr int L = F / 4;
    constexpr int NPB = 256 / L;
    int node = blockIdx.x * NPB + threadIdx.x / L;
    int lane = threadIdx.x % L;
    if (node >= NNODE) return;

    float di = dinv[node];
    int beg = g_colptr[node], end = g_colptr[node + 1];

    float4 hv = __ldg(reinterpret_cast<const float4*>(h + (size_t)node * F) + lane);
    float4 s = make_float4(di * hv.x, di * hv.y, di * hv.z, di * hv.w);

    for (int p = beg; p < end; ++p) {
        int j = g_adj_col[p];
        float dj = dinv[j];
        float4 v = __ldg(reinterpret_cast<const float4*>(h + (size_t)j * F) + lane);
        s.x += dj * v.x; s.y += dj * v.y; s.z += dj * v.z; s.w += dj * v.w;
    }

    float4 hsv = __ldg(reinterpret_cast<const float4*>(hs + (size_t)node * F) + lane);
    float4 bv  = __ldg(reinterpret_cast<const float4*>(bias) + lane);
    float rin = 1.f / ((float)g_cnt[node] + 1.f);

    float4 o;
    o.x = (di * s.x + bv.x + hsv.x) * rin;
    o.y = (di * s.y + bv.y + hsv.y) * rin;
    o.z = (di * s.z + bv.z + hsv.z) * rin;
    o.w = (di * s.w + bv.w + hsv.w) * rin;
    if (ELU) {
        o.x = o.x > 0.f ? o.x : (expf(o.x) - 1.f);
        o.y = o.y > 0.f ? o.y : (expf(o.y) - 1.f);
        o.z = o.z > 0.f ? o.z : (expf(o.z) - 1.f);
        o.w = o.w > 0.f ? o.w : (expf(o.w) - 1.f);
    }
    size_t q = (size_t)node * L + lane;
    reinterpret_cast<float4*>(out)[q] = o;
    if (f16o) {
        __half2* fp = reinterpret_cast<__half2*>(f16o) + q * 2;
        fp[0] = __halves2half2(__float2half_rn(o.x), __float2half_rn(o.y));
        fp[1] = __halves2half2(__float2half_rn(o.z), __float2half_rn(o.w));
        bf162* hp = reinterpret_cast<bf162*>(pbh) + q * 2;
        bf162* lp = reinterpret_cast<bf162*>(pbl) + q * 2;
        split2b(o.x, o.y, hp, lp);
        split2b(o.z, o.w, hp + 1, lp + 1);
    }
}

// ---------------------------------------------------------------------------
// relation elementwise over fused T = [tA | tB], emits fp32 + bf16 hi/lo
// ---------------------------------------------------------------------------
__device__ __forceinline__ float lrelu02(float v) { return v > 0.f ? v : 0.2f * v; }

__global__ void relation_ew(const float* __restrict__ x, const float* __restrict__ nb,
                            const float* __restrict__ T,
                            const float* __restrict__ m, float* __restrict__ out,
                            unsigned short* __restrict__ oh, unsigned short* __restrict__ ol,
                            int total4, int F4)
{
    int idx = blockIdx.x * blockDim.x + threadIdx.x;
    if (idx >= total4) return;
    int node = idx / F4, c = idx % F4;
    float4 xa = reinterpret_cast<const float4*>(x)[idx];
    float4 nv = reinterpret_cast<const float4*>(nb)[idx];
    float4 ta = reinterpret_cast<const float4*>(T)[(size_t)node * 2 * F4 + c];
    float4 tb = reinterpret_cast<const float4*>(T)[(size_t)node * 2 * F4 + F4 + c];
    float4 mv = reinterpret_cast<const float4*>(m)[c];

    float4 o;
    o.x = xa.x + (lrelu02(ta.x) + 1.f) * mv.x + lrelu02(tb.x) - nv.x;
    o.y = xa.y + (lrelu02(ta.y) + 1.f) * mv.y + lrelu02(tb.y) - nv.y;
    o.z = xa.z + (lrelu02(ta.z) + 1.f) * mv.z + lrelu02(tb.z) - nv.z;
    o.w = xa.w + (lrelu02(ta.w) + 1.f) * mv.w + lrelu02(tb.w) - nv.w;
    reinterpret_cast<float4*>(out)[idx] = o;

    bf162* hp = reinterpret_cast<bf162*>(oh) + (size_t)idx * 2;
    bf162* lp = reinterpret_cast<bf162*>(ol) + (size_t)idx * 2;
    split2b(o.x, o.y, hp, lp);
    split2b(o.z, o.w, hp + 1, lp + 1);
}

// ---------------------------------------------------------------------------
// fp16 2-term GEMM:  C[M,N] = sum_p A_p[M,K] @ (Bh_p + Bl_p)[N,K]^T
// A rounded fp16 (1 plane), B split fp16 hi/lo. 128 x BN_, BK=32, 256 thr.
// ---------------------------------------------------------------------------
#define SST 40

template<int BN_, int NPAIR>
__global__ __launch_bounds__(256)
void gemm_h2(const __half* __restrict__ A0, const __half* __restrict__ Bh0,
             const __half* __restrict__ Bl0,
             const __half* __restrict__ A1, const __half* __restrict__ Bh1,
             const __half* __restrict__ Bl1,
             float* __restrict__ C, int M, int N, int K)
{
    constexpr int NT  = BN_ / 32;
    constexpr int PA  = 128 * SST;
    constexpr int PB  = BN_ * SST;
    constexpr int STG = PA + 2 * PB;
    constexpr int TCH = 512 + BN_ * 8;
    constexpr int ITER = TCH / 256;

    extern __shared__ __half smh[];
    const int tid = threadIdx.x, wid = tid >> 5, lane = tid & 31;
    const int wm = wid & 1, wn = wid >> 1, grp = lane >> 2, tig = lane & 3;
    const int bm = blockIdx.y * 128, bn = blockIdx.x * BN_;

    const int KT = K / 32, TT = NPAIR * KT;

    float acc[4][NT][4];
#pragma unroll
    for (int mt = 0; mt < 4; mt++)
#pragma unroll
        for (int nt = 0; nt < NT; nt++)
#pragma unroll
            for (int q = 0; q < 4; q++) acc[mt][nt][q] = 0.f;

    auto issue = [&](int t) {
        __half* st = smh + (t & 1) * STG;
        int pair = (NPAIR == 2) ? (t / KT) : 0;
        int k0 = (t - pair * KT) * 32;
        const __half* A  = pair ? A1 : A0;
        const __half* Bh = pair ? Bh1 : Bh0;
        const __half* Bl = pair ? Bl1 : Bl0;
#pragma unroll
        for (int i = 0; i < ITER; i++) {
            int id = tid + i * 256;
            if (id < 512) {
                int row = id >> 2, ko = (id & 3) * 8;
                int gr = bm + row;
                int sz = (gr < M) ? 16 : 0;
                cpasync16(st + row * SST + ko,
                          A + (size_t)(gr < M ? gr : 0) * K + k0 + ko, sz);
            } else {
                int id2 = id - 512;
                int pl = id2 / (BN_ * 4), loc = id2 % (BN_ * 4);
                int row = loc >> 2, ko = (loc & 3) * 8;
                const __half* src = (pl ? Bl : Bh) + (size_t)(bn + row) * K + k0 + ko;
                cpasync16(st + PA + pl * PB + row * SST + ko, src, 16);
            }
        }
        cp_commit();
    };

    issue(0);
    for (int t = 0; t < TT; t++) {
        if (t + 1 < TT) {
            issue(t + 1);
            asm volatile("cp.async.wait_group 1;\n" ::: "memory");
        } else {
            asm volatile("cp.async.wait_group 0;\n" ::: "memory");
        }
        __syncthreads();

        const __half* st = smh + (t & 1) * STG;
        const __half* dBh = st + PA;
        const __half* dBl = st + PA + PB;

#pragma unroll
        for (int ks = 0; ks < 2; ks++) {
            const int kb = ks * 16;
            uint32_t a[4][4];
#pragma unroll
            for (int mt = 0; mt < 4; mt++) {
                int r0 = (wm * 64 + mt * 16 + grp) * SST + kb + 2 * tig;
                int r1 = r0 + 8 * SST;
                a[mt][0] = lds32(st, r0);     a[mt][1] = lds32(st, r1);
                a[mt][2] = lds32(st, r0 + 8); a[mt][3] = lds32(st, r1 + 8);
            }
            uint32_t bh[NT][2], bl[NT][2];
#pragma unroll
            for (int nt = 0; nt < NT; nt++) {
                int c0 = (wn * (BN_ / 4) + nt * 8 + grp) * SST + kb + 2 * tig;
                bh[nt][0] = lds32(dBh, c0); bh[nt][1] = lds32(dBh, c0 + 8);
                bl[nt][0] = lds32(dBl, c0); bl[nt][1] = lds32(dBl, c0 + 8);
            }
#pragma unroll
            for (int mt = 0; mt < 4; mt++)
#pragma unroll
                for (int nt = 0; nt < NT; nt++) {
                    mma_h(acc[mt][nt], a[mt], bh[nt]);
                    mma_h(acc[mt][nt], a[mt], bl[nt]);
                }
        }
        __syncthreads();
    }

#pragma unroll
    for (int mt = 0; mt < 4; mt++) {
        int row0 = bm + wm * 64 + mt * 16 + grp;
        int row1 = row0 + 8;
#pragma unroll
        for (int nt = 0; nt < NT; nt++) {
            int col = bn + wn * (BN_ / 4) + nt * 8 + 2 * tig;
            if (row0 < M)
                *reinterpret_cast<float2*>(C + (size_t)row0 * N + col) =
                    make_float2(acc[mt][nt][0], acc[mt][nt][1]);
            if (row1 < M)
                *reinterpret_cast<float2*>(C + (size_t)row1 * N + col) =
                    make_float2(acc[mt][nt][2], acc[mt][nt][3]);
        }
    }
}

// ---------------------------------------------------------------------------
// bf16 3-term dual-A GEMM:  C0 = (Ah0+Al0)@(Bh+Bl)^T, C1 = (Ah1+Al1)@(Bh+Bl)^T
// gridDim.y = 2*YB; blocks [0,YB) do (A0,C0), [YB,2YB) do (A1,C1).
// ---------------------------------------------------------------------------
template<int BN_>
__global__ __launch_bounds__(256)
void gemm_bf3(const bf16* __restrict__ Ah0, const bf16* __restrict__ Al0,
              const bf16* __restrict__ Ah1, const bf16* __restrict__ Al1,
              const bf16* __restrict__ Bh, const bf16* __restrict__ Bl,
              float* __restrict__ C0, float* __restrict__ C1,
              int M, int YB, int N, int K)
{
    constexpr int NT  = BN_ / 32;
    constexpr int PA  = 128 * SST;
    constexpr int PB  = BN_ * SST;
    constexpr int STG = 2 * PA + 2 * PB;
    constexpr int TCH = 1024 + BN_ * 8;
    constexpr int ITER = TCH / 256;

    extern __shared__ bf16 smb[];
    const int tid = threadIdx.x, wid = tid >> 5, lane = tid & 31;
    const int wm = wid & 1, wn = wid >> 1, grp = lane >> 2, tig = lane & 3;

    int by = blockIdx.y;
    const bf16* Ah = Ah0;
    const bf16* Al = Al0;
    float* C = C0;
    if (by >= YB) { by -= YB; Ah = Ah1; Al = Al1; C = C1; }
    const int bm = by * 128, bn = blockIdx.x * BN_;

    const int TT = K / 32;

    float acc[4][NT][4];
#pragma unroll
    for (int mt = 0; mt < 4; mt++)
#pragma unroll
        for (int nt = 0; nt < NT; nt++)
#pragma unroll
            for (int q = 0; q < 4; q++) acc[mt][nt][q] = 0.f;

    auto issue = [&](int t) {
        bf16* st = smb + (t & 1) * STG;
        int k0 = t * 32;
#pragma unroll
        for (int i = 0; i < ITER; i++) {
            int id = tid + i * 256;
            if (id < 1024) {
                int pl = id >> 9, loc = id & 511;
                int row = loc >> 2, ko = (loc & 3) * 8;
                int gr = bm + row;
                int sz = (gr < M) ? 16 : 0;
                const bf16* src = (pl ? Al : Ah) + (size_t)(gr < M ? gr : 0) * K + k0 + ko;
                cpasync16(st + pl * PA + row * SST + ko, src, sz);
            } else {
                int id2 = id - 1024;
                int pl = id2 / (BN_ * 4), loc = id2 % (BN_ * 4);
                int row = loc >> 2, ko = (loc & 3) * 8;
                const bf16* src = (pl ? Bl : Bh) + (size_t)(bn + row) * K + k0 + ko;
                cpasync16(st + 2 * PA + pl * PB + row * SST + ko, src, 16);
            }
        }
        cp_commit();
    };

    issue(0);
    for (int t = 0; t < TT; t++) {
        if (t + 1 < TT) {
            issue(t + 1);
            asm volatile("cp.async.wait_group 1;\n" ::: "memory");
        } else {
            asm volatile("cp.async.wait_group 0;\n" ::: "memory");
        }
        __syncthreads();

        const bf16* dAh = smb + (t & 1) * STG;
        const bf16* dAl = dAh + PA;
        const bf16* dBh = dAh + 2 * PA;
        const bf16* dBl = dBh + PB;

#pragma unroll
        for (int ks = 0; ks < 2; ks++) {
            const int kb = ks * 16;
            uint32_t ah[4][4], al[4][4];
#pragma unroll
            for (int mt = 0; mt < 4; mt++) {
                int r0 = (wm * 64 + mt * 16 + grp) * SST + kb + 2 * tig;
                int r1 = r0 + 8 * SST;
                ah[mt][0] = lds32(dAh, r0);     ah[mt][1] = lds32(dAh, r1);
                ah[mt][2] = lds32(dAh, r0 + 8); ah[mt][3] = lds32(dAh, r1 + 8);
                al[mt][0] = lds32(dAl, r0);     al[mt][1] = lds32(dAl, r1);
                al[mt][2] = lds32(dAl, r0 + 8); al[mt][3] = lds32(dAl, r1 + 8);
            }
            uint32_t bh[NT][2], bl[NT][2];
#pragma unroll
            for (int nt = 0; nt < NT; nt++) {
                int c0 = (wn * (BN_ / 4) + nt * 8 + grp) * SST + kb + 2 * tig;
                bh[nt][0] = lds32(dBh, c0); bh[nt][1] = lds32(dBh, c0 + 8);
                bl[nt][0] = lds32(dBl, c0); bl[nt][1] = lds32(dBl, c0 + 8);
            }
#pragma unroll
            for (int mt = 0; mt < 4; mt++)
#pragma unroll
                for (int nt = 0; nt < NT; nt++) {
                    mma_bf(acc[mt][nt], ah[mt], bh[nt]);
                    mma_bf(acc[mt][nt], ah[mt], bl[nt]);
                    mma_bf(acc[mt][nt], al[mt], bh[nt]);
                }
        }
        __syncthreads();
    }

#pragma unroll
    for (int mt = 0; mt < 4; mt++) {
        int row0 = bm + wm * 64 + mt * 16 + grp;
        int row1 = row0 + 8;
#pragma unroll
        for (int nt = 0; nt < NT; nt++) {
            int col = bn + wn * (BN_ / 4) + nt * 8 + 2 * tig;
            if (row0 < M)
                *reinterpret_cast<float2*>(C + (size_t)row0 * N + col) =
                    make_float2(acc[mt][nt][0], acc[mt][nt][1]);
            if (row1 < M)
                *reinterpret_cast<float2*>(C + (size_t)row1 * N + col) =
                    make_float2(acc[mt][nt][2], acc[mt][nt][3]);
        }
    }
}

// ---------------------------------------------------------------------------
// log_softmax over 64 columns; one warp per row
// ---------------------------------------------------------------------------
__global__ void logsoftmax64(const float* __restrict__ x, float* __restrict__ out, int n)
{
    int row = blockIdx.x * (blockDim.x >> 5) + (threadIdx.x >> 5);
    int lane = threadIdx.x & 31;
    if (row >= n) return;
    const float* xr = x + (size_t)row * 64;
    float a = xr[lane];
    float b = xr[lane + 32];
    float mx = fmaxf(a, b);
#pragma unroll
    for (int o = 16; o > 0; o >>= 1) mx = fmaxf(mx, __shfl_xor_sync(0xFFFFFFFFu, mx, o));
    float s = expf(a - mx) + expf(b - mx);
#pragma unroll
    for (int o = 16; o > 0; o >>= 1) s += __shfl_xor_sync(0xFFFFFFFFu, s, o);
    float lse = mx + logf(s);
    out[(size_t)row * 64 + lane] = a - lse;
    out[(size_t)row * 64 + lane + 32] = b - lse;
}

// ---------------------------------------------------------------------------
// Host launcher
// ---------------------------------------------------------------------------
#define SMH128  ((128 * SST + 2 * 128 * SST) * 2 * 2)            // 61440
#define SMB128  ((2 * 128 * SST + 2 * 128 * SST) * 2 * 2)        // 81920
#define SMB64   ((2 * 128 * SST + 2 * 64 * SST) * 2 * 2)         // 61440

extern "C" void kernel_launch(void* const* d_in, const int* in_sizes, int n_in,
                              void* d_out, int out_size)
{
    const float* x      = (const float*)d_in[0];
    const int*   ei_raw = (const int*)d_in[1];
    const float* r1_g1 = (const float*)d_in[3];
    const float* r1_g2 = (const float*)d_in[4];
    const float* r1_b1 = (const float*)d_in[5];
    const float* r1_b2 = (const float*)d_in[6];
    const float* r1_m  = (const float*)d_in[7];
    const float* gc1_w = (const float*)d_in[8];
    const float* gc1_b = (const float*)d_in[9];
    const float* r2_g1 = (const float*)d_in[10];
    const float* r2_g2 = (const float*)d_in[11];
    const float* r2_b1 = (const float*)d_in[12];
    const float* r2_b2 = (const float*)d_in[13];
    const float* r2_m  = (const float*)d_in[14];
    const float* gc2_w = (const float*)d_in[15];
    const float* gc2_b = (const float*)d_in[16];

    float* out = (float*)d_out;
    float* o_x2  = out;
    float* o_lsm = out + (long long)NNODE * NCLASS;
    float* o_o1  = out + 2ll * NNODE * NCLASS;
    float* o_o2  = o_o1 + (long long)NNODE * NFEAT;

    float* S = nullptr;        cudaGetSymbolAddress((void**)&S, g_scratch);
    unsigned* flag = nullptr;  cudaGetSymbolAddress((void**)&flag, g_idx_is32);
    int* cntp = nullptr;       cudaGetSymbolAddress((void**)&cntp, g_cnt);
    int* degp = nullptr;       cudaGetSymbolAddress((void**)&degp, g_deg);
    int* fillp = nullptr;      cudaGetSymbolAddress((void**)&fillp, g_fill);

    unsigned short *xf16, *nbf16, *x1f16, *xbh, *xbl, *obh, *obl, *x1bh, *x1bl;
    unsigned short *w16h, *w16l, *wbh, *wbl;
    cudaGetSymbolAddress((void**)&xf16, g_xf16);
    cudaGetSymbolAddress((void**)&nbf16, g_nbf16);
    cudaGetSymbolAddress((void**)&x1f16, g_x1f16);
    cudaGetSymbolAddress((void**)&xbh, g_xbh);   cudaGetSymbolAddress((void**)&xbl, g_xbl);
    cudaGetSymbolAddress((void**)&obh, g_obh);   cudaGetSymbolAddress((void**)&obl, g_obl);
    cudaGetSymbolAddress((void**)&x1bh, g_x1bh); cudaGetSymbolAddress((void**)&x1bl, g_x1bl);
    cudaGetSymbolAddress((void**)&w16h, g_w16h); cudaGetSymbolAddress((void**)&w16l, g_w16l);
    cudaGetSymbolAddress((void**)&wbh, g_wbh);   cudaGetSymbolAddress((void**)&wbl, g_wbl);

    float* nb1  = S + OFF_NB1;
    float* tT1  = S + OFF_TA1;   // fused [N,1024]
    float* h1   = S + OFF_H1;
    float* hs1  = S + OFF_HS1;
    float* x1   = S + OFF_X1;
    float* nb2  = S + OFF_NB2;
    float* tT2  = S + OFF_TA2;   // fused [N,512]
    float* h2   = S + OFF_H2;
    float* hs2  = S + OFF_HS2;
    float* dinv = S + OFF_DINV;

    const int N = NNODE, E = NEDGE;

    cudaFuncSetAttribute(gemm_h2<128, 2>, cudaFuncAttributeMaxDynamicSharedMemorySize, SMH128);
    cudaFuncSetAttribute(gemm_bf3<128>,   cudaFuncAttributeMaxDynamicSharedMemorySize, SMB128);
    cudaFuncSetAttribute(gemm_bf3<64>,    cudaFuncAttributeMaxDynamicSharedMemorySize, SMB64);

    cudaMemsetAsync(cntp, 0, N * sizeof(int));
    cudaMemsetAsync(degp, 0, N * sizeof(int));
    cudaMemsetAsync(fillp, 0, 2 * N * sizeof(int));
    cudaMemsetAsync(flag, 0, sizeof(unsigned));

    detect_idx<<<(E + 255) / 256, 256>>>(ei_raw);
    convert_idx<<<(2 * E + 255) / 256, 256>>>(ei_raw);

    count_int<<<(E + 255) / 256, 256>>>(E);
    scan2<<<2, 1024>>>();
    finalize_deg<<<(N + 255) / 256, 256>>>(dinv, N);
    fill_csr<<<(E + 255) / 256, 256>>>(E);

    // splits
    splitx<<<(N * NFEAT / 4 + 255) / 256, 256>>>(x, xf16, xbh, xbl, N * NFEAT / 4);
    // relation weights (fp16 h/l): layer1 [g1;b1][g2;b2], layer2 same
    splitw16<<<dim3((65536 + 255) / 256, 4), 256>>>(r1_g1, r1_b1, r1_g2, r1_b2,
                                                    w16h + W16_1A, w16l + W16_1A, 65536);
    splitw16<<<dim3((16384 + 255) / 256, 4), 256>>>(r2_g1, r2_b1, r2_g2, r2_b2,
                                                    w16h + W16_2A, w16l + W16_2A, 16384);
    // gc weights (bf16 h/l)
    splitwb<<<(32768 + 255) / 256, 256>>>(gc1_w, wbh + WB_GC1, wbl + WB_GC1, 32768);
    splitwb<<<(4096 + 255) / 256, 256>>>(gc2_w, wbh + WB_GC2, wbl + WB_GC2, 4096);

    const __half* hxf  = (const __half*)xf16;
    const __half* hnbf = (const __half*)nbf16;
    const __half* hx1f = (const __half*)x1f16;
    const __half* hw16h = (const __half*)w16h;
    const __half* hw16l = (const __half*)w16l;
    const bf16* bxh = (const bf16*)xbh, *bxl = (const bf16*)xbl;
    const bf16* boh = (const bf16*)obh, *bol = (const bf16*)obl;
    const bf16* b1h = (const bf16*)x1bh, *b1l = (const bf16*)x1bl;
    const bf16* bwh = (const bf16*)wbh,  *bwl = (const bf16*)wbl;

    // ---------------- Layer 1 ----------------
    gather_mean<NFEAT><<<(N * (NFEAT / 4) + 255) / 256, 256>>>(x, nb1, nbf16);

    // fused relation GEMM: T1 = [x|nb] @ fused-weights, N=1024, fp16 2-term
    gemm_h2<128, 2><<<dim3(8, 157), 256, SMH128>>>(
        hxf,  hw16h + W16_1A, hw16l + W16_1A,
        hnbf, hw16h + W16_1B, hw16l + W16_1B,
        tT1, N, 1024, NFEAT);
    relation_ew<<<(N * (NFEAT / 4) + 255) / 256, 256>>>(x, nb1, tT1, r1_m,
                                                        o_o1, obh, obl,
                                                        N * (NFEAT / 4), NFEAT / 4);
    // gc1: h1 = x@W^T, hs1 = o1@W^T — dual-M single launch, bf16 3-term
    gemm_bf3<128><<<dim3(2, 314), 256, SMB128>>>(
        bxh, bxl, boh, bol, bwh + WB_GC1, bwl + WB_GC1,
        h1, hs1, N, 157, NHID, NFEAT);
    gcn_fused<NHID, true><<<(N * (NHID / 4) + 255) / 256, 256>>>(
        h1, hs1, gc1_b, dinv, x1, x1f16, x1bh, x1bl);

    // ---------------- Layer 2 ----------------
    gather_mean<NHID><<<(N * (NHID / 4) + 255) / 256, 256>>>(x1, nb2, nbf16);

    gemm_h2<128, 2><<<dim3(4, 157), 256, SMH128>>>(
        hx1f, hw16h + W16_2A, hw16l + W16_2A,
        hnbf, hw16h + W16_2B, hw16l + W16_2B,
        tT2, N, 512, NHID);
    relation_ew<<<(N * (NHID / 4) + 255) / 256, 256>>>(x1, nb2, tT2, r2_m,
                                                       o_o2, obh, obl,
                                                       N * (NHID / 4), NHID / 4);
    gemm_bf3<64><<<dim3(1, 314), 256, SMB64>>>(
        b1h, b1l, boh, bol, bwh + WB_GC2, bwl + WB_GC2,
        h2, hs2, N, 157, NCLASS, NHID);
    gcn_fused<NCLASS, false><<<(N * (NCLASS / 4) + 255) / 256, 256>>>(
        h2, hs2, gc2_b, dinv, o_x2, nullptr, nullptr, nullptr);

    logsoftmax64<<<(N * 32 + 255) / 256, 256>>>(o_x2, o_lsm, N);
}

// round 15
// speedup vs baseline: 1.0042x; 1.0042x over previous
#include <cuda_runtime.h>
#include <cuda_bf16.h>
#include <cuda_fp16.h>
#include <math.h>
#include <stdint.h>

#define NNODE 20000
#define NEDGE 160000
#define NFEAT 512
#define NHID  256
#define NCLASS 64

// ---------------------------------------------------------------------------
// fp32 scratch offsets
// ---------------------------------------------------------------------------
#define OFF_NB1  0ll
#define OFF_TA1  (OFF_NB1 + (long long)NNODE*NFEAT)
#define OFF_TB1  (OFF_TA1 + (long long)NNODE*NFEAT)   // TA1+TB1 = fused T1 [N,1024]
#define OFF_H1   (OFF_TB1 + (long long)NNODE*NFEAT)
#define OFF_HS1  (OFF_H1  + (long long)NNODE*NHID)
#define OFF_X1   (OFF_HS1 + (long long)NNODE*NHID)
#define OFF_NB2  (OFF_X1  + (long long)NNODE*NHID)
#define OFF_TA2  (OFF_NB2 + (long long)NNODE*NHID)
#define OFF_TB2  (OFF_TA2 + (long long)NNODE*NHID)    // TA2+TB2 = fused T2 [N,512]
#define OFF_H2   (OFF_TB2 + (long long)NNODE*NHID)
#define OFF_HS2  (OFF_H2  + (long long)NNODE*NCLASS)
#define OFF_DINV (OFF_HS2 + (long long)NNODE*NCLASS)
#define SCRATCH_FLOATS (OFF_DINV + (long long)NNODE)

__device__ float g_scratch[SCRATCH_FLOATS];
__device__ int   g_ei32[2 * NEDGE];
__device__ unsigned g_idx_is32;
__device__ int   g_cnt[NNODE];
__device__ int   g_deg[NNODE];
__device__ int   g_rowptr[NNODE + 1];
__device__ int   g_colptr[NNODE + 1];
__device__ int   g_adj_row[NEDGE];
__device__ int   g_adj_col[NEDGE];
__device__ int   g_fill[2 * NNODE];

#define XPL   ((long long)NNODE*NFEAT)
#define X1PL  ((long long)NNODE*NHID)
// fp16 activation planes (rounded, single plane)
__device__ unsigned short g_xf16[XPL];
__device__ unsigned short g_nbf16[XPL];
__device__ unsigned short g_x1f16[X1PL];
// bf16 hi/lo activation planes (for gc GEMM A operands)
__device__ unsigned short g_xbh[XPL],  g_xbl[XPL];
__device__ unsigned short g_obh[XPL],  g_obl[XPL];
__device__ unsigned short g_x1bh[X1PL], g_x1bl[X1PL];
// fp16 hi/lo relation weight planes: [r1 g1;b1][r1 g2;b2][r2 g1;b1][r2 g2;b2]
#define W16_1A 0
#define W16_1B 524288
#define W16_2A 1048576
#define W16_2B 1179648
#define W16TOT 1310720
__device__ unsigned short g_w16h[W16TOT], g_w16l[W16TOT];
// bf16 hi/lo gc weight planes: gc1 @0 (131072), gc2 @131072 (16384)
#define WB_GC1 0
#define WB_GC2 131072
#define WBTOT  147456
__device__ unsigned short g_wbh[WBTOT], g_wbl[WBTOT];

typedef __nv_bfloat16 bf16;
typedef __nv_bfloat162 bf162;

// ---------------------------------------------------------------------------
// helpers
// ---------------------------------------------------------------------------
__device__ __forceinline__ void split2b(float x, float y, bf162* hp, bf162* lp)
{
    bf16 hx = __float2bfloat16(x);
    bf16 hy = __float2bfloat16(y);
    *hp = __halves2bfloat162(hx, hy);
    *lp = __halves2bfloat162(__float2bfloat16(x - __bfloat162float(hx)),
                             __float2bfloat16(y - __bfloat162float(hy)));
}

__device__ __forceinline__ void split2h(float x, float y, __half2* hp, __half2* lp)
{
    __half hx = __float2half_rn(x);
    __half hy = __float2half_rn(y);
    *hp = __halves2half2(hx, hy);
    *lp = __halves2half2(__float2half_rn(x - __half2float(hx)),
                         __float2half_rn(y - __half2float(hy)));
}

__device__ __forceinline__ void cpasync16(void* smem, const void* g, int sz)
{
    unsigned sa = (unsigned)__cvta_generic_to_shared(smem);
    asm volatile("cp.async.cg.shared.global [%0], [%1], 16, %2;\n"
                 :: "r"(sa), "l"(g), "r"(sz));
}
__device__ __forceinline__ void cp_commit()
{
    asm volatile("cp.async.commit_group;\n");
}

__device__ __forceinline__ void mma_bf(float* c, const uint32_t* a, const uint32_t* b)
{
    asm volatile(
        "mma.sync.aligned.m16n8k16.row.col.f32.bf16.bf16.f32 "
        "{%0,%1,%2,%3}, {%4,%5,%6,%7}, {%8,%9}, {%0,%1,%2,%3};\n"
        : "+f"(c[0]), "+f"(c[1]), "+f"(c[2]), "+f"(c[3])
        : "r"(a[0]), "r"(a[1]), "r"(a[2]), "r"(a[3]), "r"(b[0]), "r"(b[1]));
}

__device__ __forceinline__ void mma_h(float* c, const uint32_t* a, const uint32_t* b)
{
    asm volatile(
        "mma.sync.aligned.m16n8k16.row.col.f32.f16.f16.f32 "
        "{%0,%1,%2,%3}, {%4,%5,%6,%7}, {%8,%9}, {%0,%1,%2,%3};\n"
        : "+f"(c[0]), "+f"(c[1]), "+f"(c[2]), "+f"(c[3])
        : "r"(a[0]), "r"(a[1]), "r"(a[2]), "r"(a[3]), "r"(b[0]), "r"(b[1]));
}

template<typename T>
__device__ __forceinline__ uint32_t lds32(const T* s, int idx)
{
    return *reinterpret_cast<const uint32_t*>(&s[idx]);
}

// ---------------------------------------------------------------------------
// Edge-index canonicalization
// ---------------------------------------------------------------------------
__global__ void detect_idx(const int* __restrict__ raw)
{
    int i = blockIdx.x * blockDim.x + threadIdx.x;
    if (i < NEDGE) {
        if (raw[2 * i + 1] != 0) atomicOr(&g_idx_is32, 1u);
    }
}
__global__ void convert_idx(const int* __restrict__ raw)
{
    int i = blockIdx.x * blockDim.x + threadIdx.x;
    if (i < 2 * NEDGE) g_ei32[i] = g_idx_is32 ? raw[i] : raw[2 * i];
}

// ---------------------------------------------------------------------------
// CSR construction
// ---------------------------------------------------------------------------
__global__ void count_int(int E)
{
    int e = blockIdx.x * blockDim.x + threadIdx.x;
    if (e < E) {
        atomicAdd(&g_cnt[g_ei32[e]], 1);
        atomicAdd(&g_deg[g_ei32[E + e]], 1);
    }
}

__global__ __launch_bounds__(1024) void scan2()
{
    const int n = NNODE;
    const int CH = 20;
    const int* in  = blockIdx.x ? g_deg : g_cnt;
    int* out       = blockIdx.x ? g_colptr : g_rowptr;

    __shared__ int wsum[32];
    int tid = threadIdx.x, lane = tid & 31, wid = tid >> 5;
    int base = tid * CH;

    int vals[CH];
    int s = 0;
#pragma unroll
    for (int j = 0; j < CH; j++) {
        int v = (base + j < n) ? in[base + j] : 0;
        vals[j] = s;
        s += v;
    }
    int ws = s;
#pragma unroll
    for (int o = 1; o < 32; o <<= 1) {
        int t = __shfl_up_sync(0xFFFFFFFFu, ws, o);
        if (lane >= o) ws += t;
    }
    if (lane == 31) wsum[wid] = ws;
    __syncthreads();
    if (wid == 0) {
        int w = wsum[lane];
#pragma unroll
        for (int o = 1; o < 32; o <<= 1) {
            int t = __shfl_up_sync(0xFFFFFFFFu, w, o);
            if (lane >= o) w += t;
        }
        wsum[lane] = w;
    }
    __syncthreads();
    int off = (wid ? wsum[wid - 1] : 0) + ws - s;
#pragma unroll
    for (int j = 0; j < CH; j++) {
        if (base + j <= n) out[base + j] = off + vals[j];
    }
}

__global__ void fill_csr(int E)
{
    int e = blockIdx.x * blockDim.x + threadIdx.x;
    if (e < E) {
        int r = g_ei32[e];
        int c = g_ei32[E + e];
        int p = atomicAdd(&g_fill[r], 1);
        g_adj_row[g_rowptr[r] + p] = c;
        int q = atomicAdd(&g_fill[NNODE + c], 1);
        g_adj_col[g_colptr[c] + q] = r;
    }
}

__global__ void finalize_deg(float* __restrict__ dinv, int n)
{
    int i = blockIdx.x * blockDim.x + threadIdx.x;
    if (i < n) dinv[i] = rsqrtf((float)g_deg[i] + 1.f);
}

// ---------------------------------------------------------------------------
// split kernels
// ---------------------------------------------------------------------------
// x -> fp16 (rounded) + bf16 hi/lo
__global__ void splitx(const float* __restrict__ s,
                       unsigned short* __restrict__ f16,
                       unsigned short* __restrict__ bh,
                       unsigned short* __restrict__ bl, int n4)
{
    int i = blockIdx.x * blockDim.x + threadIdx.x;
    if (i >= n4) return;
    float4 v = reinterpret_cast<const float4*>(s)[i];
    __half2* fp = reinterpret_cast<__half2*>(f16) + (size_t)i * 2;
    fp[0] = __halves2half2(__float2half_rn(v.x), __float2half_rn(v.y));
    fp[1] = __halves2half2(__float2half_rn(v.z), __float2half_rn(v.w));
    bf162* hp = reinterpret_cast<bf162*>(bh) + (size_t)i * 2;
    bf162* lp = reinterpret_cast<bf162*>(bl) + (size_t)i * 2;
    split2b(v.x, v.y, hp, lp);
    split2b(v.z, v.w, hp + 1, lp + 1);
}

// up to 4 equal-size matrices -> fp16 hi/lo planes
__global__ void splitw16(const float* __restrict__ s0, const float* __restrict__ s1,
                         const float* __restrict__ s2, const float* __restrict__ s3,
                         unsigned short* __restrict__ h, unsigned short* __restrict__ l,
                         int n4)
{
    const float* s = (blockIdx.y == 0) ? s0 : (blockIdx.y == 1) ? s1
                   : (blockIdx.y == 2) ? s2 : s3;
    long long ob = (long long)blockIdx.y * n4;
    int i = blockIdx.x * blockDim.x + threadIdx.x;
    if (i >= n4) return;
    float4 v = reinterpret_cast<const float4*>(s)[i];
    __half2* hp = reinterpret_cast<__half2*>(h) + (ob + i) * 2;
    __half2* lp = reinterpret_cast<__half2*>(l) + (ob + i) * 2;
    split2h(v.x, v.y, hp, lp);
    split2h(v.z, v.w, hp + 1, lp + 1);
}

// single matrix -> bf16 hi/lo planes
__global__ void splitwb(const float* __restrict__ s,
                        unsigned short* __restrict__ h, unsigned short* __restrict__ l,
                        int n4)
{
    int i = blockIdx.x * blockDim.x + threadIdx.x;
    if (i >= n4) return;
    float4 v = reinterpret_cast<const float4*>(s)[i];
    bf162* hp = reinterpret_cast<bf162*>(h) + (size_t)i * 2;
    bf162* lp = reinterpret_cast<bf162*>(l) + (size_t)i * 2;
    split2b(v.x, v.y, hp, lp);
    split2b(v.z, v.w, hp + 1, lp + 1);
}

// ---------------------------------------------------------------------------
// Gather kernels (atomic-free)
// ---------------------------------------------------------------------------
template<int F>
__global__ __launch_bounds__(256)
void gather_mean(const float* __restrict__ x, float* __restrict__ nb,
                 unsigned short* __restrict__ nbf16)
{
    constexpr int L = F / 4;
    constexpr int NPB = 256 / L;
    int node = blockIdx.x * NPB + threadIdx.x / L;
    int lane = threadIdx.x % L;
    if (node >= NNODE) return;

    int beg = g_rowptr[node], end = g_rowptr[node + 1];
    float4 s = make_float4(0.f, 0.f, 0.f, 0.f);
    for (int p = beg; p < end; ++p) {
        int j = g_adj_row[p];
        float4 v = __ldg(reinterpret_cast<const float4*>(x + (size_t)j * F) + lane);
        s.x += v.x; s.y += v.y; s.z += v.z; s.w += v.w;
    }
    int c = end - beg;
    float inv = (c > 0) ? 1.f / (float)c : 0.f;
    s.x *= inv; s.y *= inv; s.z *= inv; s.w *= inv;
    size_t q = (size_t)node * L + lane;
    reinterpret_cast<float4*>(nb)[q] = s;
    __half2* fp = reinterpret_cast<__half2*>(nbf16) + q * 2;
    fp[0] = __halves2half2(__float2half_rn(s.x), __float2half_rn(s.y));
    fp[1] = __halves2half2(__float2half_rn(s.z), __float2half_rn(s.w));
}

template<int F, bool ELU>
__global__ __launch_bounds__(256)
void gcn_fused(const float* __restrict__ h, const float* __restrict__ hs,
               const float* __restrict__ bias, const float* __restrict__ dinv,
               float* __restrict__ out,
               unsigned short* __restrict__ f16o,
               unsigned short* __restrict__ pbh, unsigned short* __restrict__ pbl)
{
    constexpr int L = F / 4;
    constexpr int NPB = 256 / L;
    int node = blockIdx.x * NPB + threadIdx.x / L;
    int lane = threadIdx.x % L;
    if (node >= NNODE) return;

    float di = dinv[node];
    int beg = g_colptr[node], end = g_colptr[node + 1];

    float4 hv = __ldg(reinterpret_cast<const float4*>(h + (size_t)node * F) + lane);
    float4 s = make_float4(di * hv.x, di * hv.y, di * hv.z, di * hv.w);

    for (int p = beg; p < end; ++p) {
        int j = g_adj_col[p];
        float dj = dinv[j];
        float4 v = __ldg(reinterpret_cast<const float4*>(h + (size_t)j * F) + lane);
        s.x += dj * v.x; s.y += dj * v.y; s.z += dj * v.z; s.w += dj * v.w;
    }

    float4 hsv = __ldg(reinterpret_cast<const float4*>(hs + (size_t)node * F) + lane);
    float4 bv  = __ldg(reinterpret_cast<const float4*>(bias) + lane);
    float rin = 1.f / ((float)g_cnt[node] + 1.f);

    float4 o;
    o.x = (di * s.x + bv.x + hsv.x) * rin;
    o.y = (di * s.y + bv.y + hsv.y) * rin;
    o.z = (di * s.z + bv.z + hsv.z) * rin;
    o.w = (di * s.w + bv.w + hsv.w) * rin;
    if (ELU) {
        o.x = o.x > 0.f ? o.x : (expf(o.x) - 1.f);
        o.y = o.y > 0.f ? o.y : (expf(o.y) - 1.f);
        o.z = o.z > 0.f ? o.z : (expf(o.z) - 1.f);
        o.w = o.w > 0.f ? o.w : (expf(o.w) - 1.f);
    }
    size_t q = (size_t)node * L + lane;
    reinterpret_cast<float4*>(out)[q] = o;
    if (f16o) {
        __half2* fp = reinterpret_cast<__half2*>(f16o) + q * 2;
        fp[0] = __halves2half2(__float2half_rn(o.x), __float2half_rn(o.y));
        fp[1] = __halves2half2(__float2half_rn(o.z), __float2half_rn(o.w));
        bf162* hp = reinterpret_cast<bf162*>(pbh) + q * 2;
        bf162* lp = reinterpret_cast<bf162*>(pbl) + q * 2;
        split2b(o.x, o.y, hp, lp);
        split2b(o.z, o.w, hp + 1, lp + 1);
    }
}

// ---------------------------------------------------------------------------
// relation elementwise over fused T = [tA | tB], emits fp32 + bf16 hi/lo
// ---------------------------------------------------------------------------
__device__ __forceinline__ float lrelu02(float v) { return v > 0.f ? v : 0.2f * v; }

__global__ void relation_ew(const float* __restrict__ x, const float* __restrict__ nb,
                            const float* __restrict__ T,
                            const float* __restrict__ m, float* __restrict__ out,
                            unsigned short* __restrict__ oh, unsigned short* __restrict__ ol,
                            int total4, int F4)
{
    int idx = blockIdx.x * blockDim.x + threadIdx.x;
    if (idx >= total4) return;
    int node = idx / F4, c = idx % F4;
    float4 xa = reinterpret_cast<const float4*>(x)[idx];
    float4 nv = reinterpret_cast<const float4*>(nb)[idx];
    float4 ta = reinterpret_cast<const float4*>(T)[(size_t)node * 2 * F4 + c];
    float4 tb = reinterpret_cast<const float4*>(T)[(size_t)node * 2 * F4 + F4 + c];
    float4 mv = reinterpret_cast<const float4*>(m)[c];

    float4 o;
    o.x = xa.x + (lrelu02(ta.x) + 1.f) * mv.x + lrelu02(tb.x) - nv.x;
    o.y = xa.y + (lrelu02(ta.y) + 1.f) * mv.y + lrelu02(tb.y) - nv.y;
    o.z = xa.z + (lrelu02(ta.z) + 1.f) * mv.z + lrelu02(tb.z) - nv.z;
    o.w = xa.w + (lrelu02(ta.w) + 1.f) * mv.w + lrelu02(tb.w) - nv.w;
    reinterpret_cast<float4*>(out)[idx] = o;

    bf162* hp = reinterpret_cast<bf162*>(oh) + (size_t)idx * 2;
    bf162* lp = reinterpret_cast<bf162*>(ol) + (size_t)idx * 2;
    split2b(o.x, o.y, hp, lp);
    split2b(o.z, o.w, hp + 1, lp + 1);
}

// ---------------------------------------------------------------------------
// fp16 2-term GEMM:  C[M,N] = sum_p A_p[M,K] @ (Bh_p + Bl_p)[N,K]^T
// A rounded fp16 (1 plane), B split fp16 hi/lo. 128 x BN_, BK=32, 256 thr.
// ---------------------------------------------------------------------------
#define SST 40

template<int BN_, int NPAIR>
__global__ __launch_bounds__(256)
void gemm_h2(const __half* __restrict__ A0, const __half* __restrict__ Bh0,
             const __half* __restrict__ Bl0,
             const __half* __restrict__ A1, const __half* __restrict__ Bh1,
             const __half* __restrict__ Bl1,
             float* __restrict__ C, int M, int N, int K)
{
    constexpr int NT  = BN_ / 32;
    constexpr int PA  = 128 * SST;
    constexpr int PB  = BN_ * SST;
    constexpr int STG = PA + 2 * PB;
    constexpr int TCH = 512 + BN_ * 8;
    constexpr int ITER = TCH / 256;

    extern __shared__ __half smh[];
    const int tid = threadIdx.x, wid = tid >> 5, lane = tid & 31;
    const int wm = wid & 1, wn = wid >> 1, grp = lane >> 2, tig = lane & 3;
    const int bm = blockIdx.y * 128, bn = blockIdx.x * BN_;

    const int KT = K / 32, TT = NPAIR * KT;

    float acc[4][NT][4];
#pragma unroll
    for (int mt = 0; mt < 4; mt++)
#pragma unroll
        for (int nt = 0; nt < NT; nt++)
#pragma unroll
            for (int q = 0; q < 4; q++) acc[mt][nt][q] = 0.f;

    auto issue = [&](int t) {
        __half* st = smh + (t & 1) * STG;
        int pair = (NPAIR == 2) ? (t / KT) : 0;
        int k0 = (t - pair * KT) * 32;
        const __half* A  = pair ? A1 : A0;
        const __half* Bh = pair ? Bh1 : Bh0;
        const __half* Bl = pair ? Bl1 : Bl0;
#pragma unroll
        for (int i = 0; i < ITER; i++) {
            int id = tid + i * 256;
            if (id < 512) {
                int row = id >> 2, ko = (id & 3) * 8;
                int gr = bm + row;
                int sz = (gr < M) ? 16 : 0;
                cpasync16(st + row * SST + ko,
                          A + (size_t)(gr < M ? gr : 0) * K + k0 + ko, sz);
            } else {
                int id2 = id - 512;
                int pl = id2 / (BN_ * 4), loc = id2 % (BN_ * 4);
                int row = loc >> 2, ko = (loc & 3) * 8;
                const __half* src = (pl ? Bl : Bh) + (size_t)(bn + row) * K + k0 + ko;
                cpasync16(st + PA + pl * PB + row * SST + ko, src, 16);
            }
        }
        cp_commit();
    };

    issue(0);
    for (int t = 0; t < TT; t++) {
        if (t + 1 < TT) {
            issue(t + 1);
            asm volatile("cp.async.wait_group 1;\n" ::: "memory");
        } else {
            asm volatile("cp.async.wait_group 0;\n" ::: "memory");
        }
        __syncthreads();

        const __half* st = smh + (t & 1) * STG;
        const __half* dBh = st + PA;
        const __half* dBl = st + PA + PB;

#pragma unroll
        for (int ks = 0; ks < 2; ks++) {
            const int kb = ks * 16;
            uint32_t a[4][4];
#pragma unroll
            for (int mt = 0; mt < 4; mt++) {
                int r0 = (wm * 64 + mt * 16 + grp) * SST + kb + 2 * tig;
                int r1 = r0 + 8 * SST;
                a[mt][0] = lds32(st, r0);     a[mt][1] = lds32(st, r1);
                a[mt][2] = lds32(st, r0 + 8); a[mt][3] = lds32(st, r1 + 8);
            }
            uint32_t bh[NT][2], bl[NT][2];
#pragma unroll
            for (int nt = 0; nt < NT; nt++) {
                int c0 = (wn * (BN_ / 4) + nt * 8 + grp) * SST + kb + 2 * tig;
                bh[nt][0] = lds32(dBh, c0); bh[nt][1] = lds32(dBh, c0 + 8);
                bl[nt][0] = lds32(dBl, c0); bl[nt][1] = lds32(dBl, c0 + 8);
            }
#pragma unroll
            for (int mt = 0; mt < 4; mt++)
#pragma unroll
                for (int nt = 0; nt < NT; nt++) {
                    mma_h(acc[mt][nt], a[mt], bh[nt]);
                    mma_h(acc[mt][nt], a[mt], bl[nt]);
                }
        }
        __syncthreads();
    }

#pragma unroll
    for (int mt = 0; mt < 4; mt++) {
        int row0 = bm + wm * 64 + mt * 16 + grp;
        int row1 = row0 + 8;
#pragma unroll
        for (int nt = 0; nt < NT; nt++) {
            int col = bn + wn * (BN_ / 4) + nt * 8 + 2 * tig;
            if (row0 < M)
                *reinterpret_cast<float2*>(C + (size_t)row0 * N + col) =
                    make_float2(acc[mt][nt][0], acc[mt][nt][1]);
            if (row1 < M)
                *reinterpret_cast<float2*>(C + (size_t)row1 * N + col) =
                    make_float2(acc[mt][nt][2], acc[mt][nt][3]);
        }
    }
}

// ---------------------------------------------------------------------------
// bf16 3-term dual-A GEMM:  C0 = (Ah0+Al0)@(Bh+Bl)^T, C1 = (Ah1+Al1)@(Bh+Bl)^T
// gridDim.y = 2*YB; blocks [0,YB) do (A0,C0), [YB,2YB) do (A1,C1).
// ---------------------------------------------------------------------------
template<int BN_>
__global__ __launch_bounds__(256)
void gemm_bf3(const bf16* __restrict__ Ah0, const bf16* __restrict__ Al0,
              const bf16* __restrict__ Ah1, const bf16* __restrict__ Al1,
              const bf16* __restrict__ Bh, const bf16* __restrict__ Bl,
              float* __restrict__ C0, float* __restrict__ C1,
              int M, int YB, int N, int K)
{
    constexpr int NT  = BN_ / 32;
    constexpr int PA  = 128 * SST;
    constexpr int PB  = BN_ * SST;
    constexpr int STG = 2 * PA + 2 * PB;
    constexpr int TCH = 1024 + BN_ * 8;
    constexpr int ITER = TCH / 256;

    extern __shared__ bf16 smb[];
    const int tid = threadIdx.x, wid = tid >> 5, lane = tid & 31;
    const int wm = wid & 1, wn = wid >> 1, grp = lane >> 2, tig = lane & 3;

    int by = blockIdx.y;
    const bf16* Ah = Ah0;
    const bf16* Al = Al0;
    float* C = C0;
    if (by >= YB) { by -= YB; Ah = Ah1; Al = Al1; C = C1; }
    const int bm = by * 128, bn = blockIdx.x * BN_;

    const int TT = K / 32;

    float acc[4][NT][4];
#pragma unroll
    for (int mt = 0; mt < 4; mt++)
#pragma unroll
        for (int nt = 0; nt < NT; nt++)
#pragma unroll
            for (int q = 0; q < 4; q++) acc[mt][nt][q] = 0.f;

    auto issue = [&](int t) {
        bf16* st = smb + (t & 1) * STG;
        int k0 = t * 32;
#pragma unroll
        for (int i = 0; i < ITER; i++) {
            int id = tid + i * 256;
            if (id < 1024) {
                int pl = id >> 9, loc = id & 511;
                int row = loc >> 2, ko = (loc & 3) * 8;
                int gr = bm + row;
                int sz = (gr < M) ? 16 : 0;
                const bf16* src = (pl ? Al : Ah) + (size_t)(gr < M ? gr : 0) * K + k0 + ko;
                cpasync16(st + pl * PA + row * SST + ko, src, sz);
            } else {
                int id2 = id - 1024;
                int pl = id2 / (BN_ * 4), loc = id2 % (BN_ * 4);
                int row = loc >> 2, ko = (loc & 3) * 8;
                const bf16* src = (pl ? Bl : Bh) + (size_t)(bn + row) * K + k0 + ko;
                cpasync16(st + 2 * PA + pl * PB + row * SST + ko, src, 16);
            }
        }
        cp_commit();
    };

    issue(0);
    for (int t = 0; t < TT; t++) {
        if (t + 1 < TT) {
            issue(t + 1);
            asm volatile("cp.async.wait_group 1;\n" ::: "memory");
        } else {
            asm volatile("cp.async.wait_group 0;\n" ::: "memory");
        }
        __syncthreads();

        const bf16* dAh = smb + (t & 1) * STG;
        const bf16* dAl = dAh + PA;
        const bf16* dBh = dAh + 2 * PA;
        const bf16* dBl = dBh + PB;

#pragma unroll
        for (int ks = 0; ks < 2; ks++) {
            const int kb = ks * 16;
            uint32_t ah[4][4], al[4][4];
#pragma unroll
            for (int mt = 0; mt < 4; mt++) {
                int r0 = (wm * 64 + mt * 16 + grp) * SST + kb + 2 * tig;
                int r1 = r0 + 8 * SST;
                ah[mt][0] = lds32(dAh, r0);     ah[mt][1] = lds32(dAh, r1);
                ah[mt][2] = lds32(dAh, r0 + 8); ah[mt][3] = lds32(dAh, r1 + 8);
                al[mt][0] = lds32(dAl, r0);     al[mt][1] = lds32(dAl, r1);
                al[mt][2] = lds32(dAl, r0 + 8); al[mt][3] = lds32(dAl, r1 + 8);
            }
            uint32_t bh[NT][2], bl[NT][2];
#pragma unroll
            for (int nt = 0; nt < NT; nt++) {
                int c0 = (wn * (BN_ / 4) + nt * 8 + grp) * SST + kb + 2 * tig;
                bh[nt][0] = lds32(dBh, c0); bh[nt][1] = lds32(dBh, c0 + 8);
                bl[nt][0] = lds32(dBl, c0); bl[nt][1] = lds32(dBl, c0 + 8);
            }
#pragma unroll
            for (int mt = 0; mt < 4; mt++)
#pragma unroll
                for (int nt = 0; nt < NT; nt++) {
                    mma_bf(acc[mt][nt], ah[mt], bh[nt]);
                    mma_bf(acc[mt][nt], ah[mt], bl[nt]);
                    mma_bf(acc[mt][nt], al[mt], bh[nt]);
                }
        }
        __syncthreads();
    }

#pragma unroll
    for (int mt = 0; mt < 4; mt++) {
        int row0 = bm + wm * 64 + mt * 16 + grp;
        int row1 = row0 + 8;
#pragma unroll
        for (int nt = 0; nt < NT; nt++) {
            int col = bn + wn * (BN_ / 4) + nt * 8 + 2 * tig;
            if (row0 < M)
                *reinterpret_cast<float2*>(C + (size_t)row0 * N + col) =
                    make_float2(acc[mt][nt][0], acc[mt][nt][1]);
            if (row1 < M)
                *reinterpret_cast<float2*>(C + (size_t)row1 * N + col) =
                    make_float2(acc[mt][nt][2], acc[mt][nt][3]);
        }
    }
}

// ---------------------------------------------------------------------------
// log_softmax over 64 columns; one warp per row
// ---------------------------------------------------------------------------
__global__ void logsoftmax64(const float* __restrict__ x, float* __restrict__ out, int n)
{
    int row = blockIdx.x * (blockDim.x >> 5) + (threadIdx.x >> 5);
    int lane = threadIdx.x & 31;
    if (row >= n) return;
    const float* xr = x + (size_t)row * 64;
    float a = xr[lane];
    float b = xr[lane + 32];
    float mx = fmaxf(a, b);
#pragma unroll
    for (int o = 16; o > 0; o >>= 1) mx = fmaxf(mx, __shfl_xor_sync(0xFFFFFFFFu, mx, o));
    float s = expf(a - mx) + expf(b - mx);
#pragma unroll
    for (int o = 16; o > 0; o >>= 1) s += __shfl_xor_sync(0xFFFFFFFFu, s, o);
    float lse = mx + logf(s);
    out[(size_t)row * 64 + lane] = a - lse;
    out[(size_t)row * 64 + lane + 32] = b - lse;
}

// ---------------------------------------------------------------------------
// Host launcher
// ---------------------------------------------------------------------------
#define SMH128  ((128 * SST + 2 * 128 * SST) * 2 * 2)            // 61440
#define SMB128  ((2 * 128 * SST + 2 * 128 * SST) * 2 * 2)        // 81920
#define SMB64   ((2 * 128 * SST + 2 * 64 * SST) * 2 * 2)         // 61440

extern "C" void kernel_launch(void* const* d_in, const int* in_sizes, int n_in,
                              void* d_out, int out_size)
{
    const float* x      = (const float*)d_in[0];
    const int*   ei_raw = (const int*)d_in[1];
    const float* r1_g1 = (const float*)d_in[3];
    const float* r1_g2 = (const float*)d_in[4];
    const float* r1_b1 = (const float*)d_in[5];
    const float* r1_b2 = (const float*)d_in[6];
    const float* r1_m  = (const float*)d_in[7];
    const float* gc1_w = (const float*)d_in[8];
    const float* gc1_b = (const float*)d_in[9];
    const float* r2_g1 = (const float*)d_in[10];
    const float* r2_g2 = (const float*)d_in[11];
    const float* r2_b1 = (const float*)d_in[12];
    const float* r2_b2 = (const float*)d_in[13];
    const float* r2_m  = (const float*)d_in[14];
    const float* gc2_w = (const float*)d_in[15];
    const float* gc2_b = (const float*)d_in[16];

    float* out = (float*)d_out;
    float* o_x2  = out;
    float* o_lsm = out + (long long)NNODE * NCLASS;
    float* o_o1  = out + 2ll * NNODE * NCLASS;
    float* o_o2  = o_o1 + (long long)NNODE * NFEAT;

    float* S = nullptr;        cudaGetSymbolAddress((void**)&S, g_scratch);
    unsigned* flag = nullptr;  cudaGetSymbolAddress((void**)&flag, g_idx_is32);
    int* cntp = nullptr;       cudaGetSymbolAddress((void**)&cntp, g_cnt);
    int* degp = nullptr;       cudaGetSymbolAddress((void**)&degp, g_deg);
    int* fillp = nullptr;      cudaGetSymbolAddress((void**)&fillp, g_fill);

    unsigned short *xf16, *nbf16, *x1f16, *xbh, *xbl, *obh, *obl, *x1bh, *x1bl;
    unsigned short *w16h, *w16l, *wbh, *wbl;
    cudaGetSymbolAddress((void**)&xf16, g_xf16);
    cudaGetSymbolAddress((void**)&nbf16, g_nbf16);
    cudaGetSymbolAddress((void**)&x1f16, g_x1f16);
    cudaGetSymbolAddress((void**)&xbh, g_xbh);   cudaGetSymbolAddress((void**)&xbl, g_xbl);
    cudaGetSymbolAddress((void**)&obh, g_obh);   cudaGetSymbolAddress((void**)&obl, g_obl);
    cudaGetSymbolAddress((void**)&x1bh, g_x1bh); cudaGetSymbolAddress((void**)&x1bl, g_x1bl);
    cudaGetSymbolAddress((void**)&w16h, g_w16h); cudaGetSymbolAddress((void**)&w16l, g_w16l);
    cudaGetSymbolAddress((void**)&wbh, g_wbh);   cudaGetSymbolAddress((void**)&wbl, g_wbl);

    float* nb1  = S + OFF_NB1;
    float* tT1  = S + OFF_TA1;   // fused [N,1024]
    float* h1   = S + OFF_H1;
    float* hs1  = S + OFF_HS1;
    float* x1   = S + OFF_X1;
    float* nb2  = S + OFF_NB2;
    float* tT2  = S + OFF_TA2;   // fused [N,512]
    float* h2   = S + OFF_H2;
    float* hs2  = S + OFF_HS2;
    float* dinv = S + OFF_DINV;

    const int N = NNODE, E = NEDGE;

    cudaFuncSetAttribute(gemm_h2<128, 2>, cudaFuncAttributeMaxDynamicSharedMemorySize, SMH128);
    cudaFuncSetAttribute(gemm_bf3<128>,   cudaFuncAttributeMaxDynamicSharedMemorySize, SMB128);
    cudaFuncSetAttribute(gemm_bf3<64>,    cudaFuncAttributeMaxDynamicSharedMemorySize, SMB64);

    cudaMemsetAsync(cntp, 0, N * sizeof(int));
    cudaMemsetAsync(degp, 0, N * sizeof(int));
    cudaMemsetAsync(fillp, 0, 2 * N * sizeof(int));
    cudaMemsetAsync(flag, 0, sizeof(unsigned));

    detect_idx<<<(E + 255) / 256, 256>>>(ei_raw);
    convert_idx<<<(2 * E + 255) / 256, 256>>>(ei_raw);

    count_int<<<(E + 255) / 256, 256>>>(E);
    scan2<<<2, 1024>>>();
    finalize_deg<<<(N + 255) / 256, 256>>>(dinv, N);
    fill_csr<<<(E + 255) / 256, 256>>>(E);

    // splits
    splitx<<<(N * NFEAT / 4 + 255) / 256, 256>>>(x, xf16, xbh, xbl, N * NFEAT / 4);
    // relation weights (fp16 h/l): layer1 [g1;b1][g2;b2], layer2 same
    splitw16<<<dim3((65536 + 255) / 256, 4), 256>>>(r1_g1, r1_b1, r1_g2, r1_b2,
                                                    w16h + W16_1A, w16l + W16_1A, 65536);
    splitw16<<<dim3((16384 + 255) / 256, 4), 256>>>(r2_g1, r2_b1, r2_g2, r2_b2,
                                                    w16h + W16_2A, w16l + W16_2A, 16384);
    // gc weights (bf16 h/l)
    splitwb<<<(32768 + 255) / 256, 256>>>(gc1_w, wbh + WB_GC1, wbl + WB_GC1, 32768);
    splitwb<<<(4096 + 255) / 256, 256>>>(gc2_w, wbh + WB_GC2, wbl + WB_GC2, 4096);

    const __half* hxf  = (const __half*)xf16;
    const __half* hnbf = (const __half*)nbf16;
    const __half* hx1f = (const __half*)x1f16;
    const __half* hw16h = (const __half*)w16h;
    const __half* hw16l = (const __half*)w16l;
    const bf16* bxh = (const bf16*)xbh, *bxl = (const bf16*)xbl;
    const bf16* boh = (const bf16*)obh, *bol = (const bf16*)obl;
    const bf16* b1h = (const bf16*)x1bh, *b1l = (const bf16*)x1bl;
    const bf16* bwh = (const bf16*)wbh,  *bwl = (const bf16*)wbl;

    // ---------------- Layer 1 ----------------
    gather_mean<NFEAT><<<(N * (NFEAT / 4) + 255) / 256, 256>>>(x, nb1, nbf16);

    // fused relation GEMM: T1 = [x|nb] @ fused-weights, N=1024, fp16 2-term
    gemm_h2<128, 2><<<dim3(8, 157), 256, SMH128>>>(
        hxf,  hw16h + W16_1A, hw16l + W16_1A,
        hnbf, hw16h + W16_1B, hw16l + W16_1B,
        tT1, N, 1024, NFEAT);
    relation_ew<<<(N * (NFEAT / 4) + 255) / 256, 256>>>(x, nb1, tT1, r1_m,
                                                        o_o1, obh, obl,
                                                        N * (NFEAT / 4), NFEAT / 4);
    // gc1: h1 = x@W^T, hs1 = o1@W^T — dual-M single launch, bf16 3-term
    gemm_bf3<128><<<dim3(2, 314), 256, SMB128>>>(
        bxh, bxl, boh, bol, bwh + WB_GC1, bwl + WB_GC1,
        h1, hs1, N, 157, NHID, NFEAT);
    gcn_fused<NHID, true><<<(N * (NHID / 4) + 255) / 256, 256>>>(
        h1, hs1, gc1_b, dinv, x1, x1f16, x1bh, x1bl);

    // ---------------- Layer 2 ----------------
    gather_mean<NHID><<<(N * (NHID / 4) + 255) / 256, 256>>>(x1, nb2, nbf16);

    gemm_h2<128, 2><<<dim3(4, 157), 256, SMH128>>>(
        hx1f, hw16h + W16_2A, hw16l + W16_2A,
        hnbf, hw16h + W16_2B, hw16l + W16_2B,
        tT2, N, 512, NHID);
    relation_ew<<<(N * (NHID / 4) + 255) / 256, 256>>>(x1, nb2, tT2, r2_m,
                                                       o_o2, obh, obl,
                                                       N * (NHID / 4), NHID / 4);
    gemm_bf3<64><<<dim3(1, 314), 256, SMB64>>>(
        b1h, b1l, boh, bol, bwh + WB_GC2, bwl + WB_GC2,
        h2, hs2, N, 157, NCLASS, NHID);
    gcn_fused<NCLASS, false><<<(N * (NCLASS / 4) + 255) / 256, 256>>>(
        h2, hs2, gc2_b, dinv, o_x2, nullptr, nullptr, nullptr);

    logsoftmax64<<<(N * 32 + 255) / 256, 256>>>(o_x2, o_lsm, N);
}

// round 16
// speedup vs baseline: 1.0047x; 1.0005x over previous
#include <cuda_runtime.h>
#include <cuda_bf16.h>
#include <cuda_fp16.h>
#include <math.h>
#include <stdint.h>

#define NNODE 20000
#define NEDGE 160000
#define NFEAT 512
#define NHID  256
#define NCLASS 64

// ---------------------------------------------------------------------------
// fp32 scratch offsets
// ---------------------------------------------------------------------------
#define OFF_NB1  0ll
#define OFF_TA1  (OFF_NB1 + (long long)NNODE*NFEAT)
#define OFF_TB1  (OFF_TA1 + (long long)NNODE*NFEAT)   // TA1+TB1 = fused T1 [N,1024]
#define OFF_H1   (OFF_TB1 + (long long)NNODE*NFEAT)
#define OFF_HS1  (OFF_H1  + (long long)NNODE*NHID)
#define OFF_X1   (OFF_HS1 + (long long)NNODE*NHID)
#define OFF_NB2  (OFF_X1  + (long long)NNODE*NHID)
#define OFF_TA2  (OFF_NB2 + (long long)NNODE*NHID)
#define OFF_TB2  (OFF_TA2 + (long long)NNODE*NHID)    // TA2+TB2 = fused T2 [N,512]
#define OFF_H2   (OFF_TB2 + (long long)NNODE*NHID)
#define OFF_HS2  (OFF_H2  + (long long)NNODE*NCLASS)
#define OFF_DINV (OFF_HS2 + (long long)NNODE*NCLASS)
#define SCRATCH_FLOATS (OFF_DINV + (long long)NNODE)

__device__ float g_scratch[SCRATCH_FLOATS];
__device__ int   g_ei32[2 * NEDGE];
__device__ unsigned g_idx_is32;
__device__ int   g_cnt[NNODE];
__device__ int   g_deg[NNODE];
__device__ int   g_rowptr[NNODE + 1];
__device__ int   g_colptr[NNODE + 1];
__device__ int   g_adj_row[NEDGE];
__device__ int   g_adj_col[NEDGE];
__device__ int   g_fill[2 * NNODE];

#define XPL   ((long long)NNODE*NFEAT)
#define X1PL  ((long long)NNODE*NHID)
// fp16 activation planes (rounded, single plane)
__device__ unsigned short g_xf16[XPL];
__device__ unsigned short g_nbf16[XPL];
__device__ unsigned short g_x1f16[X1PL];
// bf16 hi/lo activation planes (for gc GEMM A operands)
__device__ unsigned short g_xbh[XPL],  g_xbl[XPL];
__device__ unsigned short g_obh[XPL],  g_obl[XPL];
__device__ unsigned short g_x1bh[X1PL], g_x1bl[X1PL];
// fp16 hi/lo relation weight planes: [r1 g1;b1][r1 g2;b2][r2 g1;b1][r2 g2;b2]
#define W16_1A 0
#define W16_1B 524288
#define W16_2A 1048576
#define W16_2B 1179648
#define W16TOT 1310720
__device__ unsigned short g_w16h[W16TOT], g_w16l[W16TOT];
// bf16 hi/lo gc weight planes: gc1 @0 (131072), gc2 @131072 (16384)
#define WB_GC1 0
#define WB_GC2 131072
#define WBTOT  147456
__device__ unsigned short g_wbh[WBTOT], g_wbl[WBTOT];

typedef __nv_bfloat16 bf16;
typedef __nv_bfloat162 bf162;

// ---------------------------------------------------------------------------
// helpers
// ---------------------------------------------------------------------------
__device__ __forceinline__ void split2b(float x, float y, bf162* hp, bf162* lp)
{
    bf16 hx = __float2bfloat16(x);
    bf16 hy = __float2bfloat16(y);
    *hp = __halves2bfloat162(hx, hy);
    *lp = __halves2bfloat162(__float2bfloat16(x - __bfloat162float(hx)),
                             __float2bfloat16(y - __bfloat162float(hy)));
}

__device__ __forceinline__ void split2h(float x, float y, __half2* hp, __half2* lp)
{
    __half hx = __float2half_rn(x);
    __half hy = __float2half_rn(y);
    *hp = __halves2half2(hx, hy);
    *lp = __halves2half2(__float2half_rn(x - __half2float(hx)),
                         __float2half_rn(y - __half2float(hy)));
}

__device__ __forceinline__ void cpasync16(void* smem, const void* g, int sz)
{
    unsigned sa = (unsigned)__cvta_generic_to_shared(smem);
    asm volatile("cp.async.cg.shared.global [%0], [%1], 16, %2;\n"
                 :: "r"(sa), "l"(g), "r"(sz));
}
__device__ __forceinline__ void cp_commit()
{
    asm volatile("cp.async.commit_group;\n");
}

__device__ __forceinline__ void mma_bf(float* c, const uint32_t* a, const uint32_t* b)
{
    asm volatile(
        "mma.sync.aligned.m16n8k16.row.col.f32.bf16.bf16.f32 "
        "{%0,%1,%2,%3}, {%4,%5,%6,%7}, {%8,%9}, {%0,%1,%2,%3};\n"
        : "+f"(c[0]), "+f"(c[1]), "+f"(c[2]), "+f"(c[3])
        : "r"(a[0]), "r"(a[1]), "r"(a[2]), "r"(a[3]), "r"(b[0]), "r"(b[1]));
}

__device__ __forceinline__ void mma_h(float* c, const uint32_t* a, const uint32_t* b)
{
    asm volatile(
        "mma.sync.aligned.m16n8k16.row.col.f32.f16.f16.f32 "
        "{%0,%1,%2,%3}, {%4,%5,%6,%7}, {%8,%9}, {%0,%1,%2,%3};\n"
        : "+f"(c[0]), "+f"(c[1]), "+f"(c[2]), "+f"(c[3])
        : "r"(a[0]), "r"(a[1]), "r"(a[2]), "r"(a[3]), "r"(b[0]), "r"(b[1]));
}

template<typename T>
__device__ __forceinline__ uint32_t lds32(const T* s, int idx)
{
    return *reinterpret_cast<const uint32_t*>(&s[idx]);
}

// ---------------------------------------------------------------------------
// Edge-index canonicalization
// ---------------------------------------------------------------------------
__global__ void detect_idx(const int* __restrict__ raw)
{
    int i = blockIdx.x * blockDim.x + threadIdx.x;
    if (i < NEDGE) {
        if (raw[2 * i + 1] != 0) atomicOr(&g_idx_is32, 1u);
    }
}
__global__ void convert_idx(const int* __restrict__ raw)
{
    int i = blockIdx.x * blockDim.x + threadIdx.x;
    if (i < 2 * NEDGE) g_ei32[i] = g_idx_is32 ? raw[i] : raw[2 * i];
}

// ---------------------------------------------------------------------------
// CSR construction
// ---------------------------------------------------------------------------
__global__ void count_int(int E)
{
    int e = blockIdx.x * blockDim.x + threadIdx.x;
    if (e < E) {
        atomicAdd(&g_cnt[g_ei32[e]], 1);
        atomicAdd(&g_deg[g_ei32[E + e]], 1);
    }
}

__global__ __launch_bounds__(1024) void scan2()
{
    const int n = NNODE;
    const int CH = 20;
    const int* in  = blockIdx.x ? g_deg : g_cnt;
    int* out       = blockIdx.x ? g_colptr : g_rowptr;

    __shared__ int wsum[32];
    int tid = threadIdx.x, lane = tid & 31, wid = tid >> 5;
    int base = tid * CH;

    int vals[CH];
    int s = 0;
#pragma unroll
    for (int j = 0; j < CH; j++) {
        int v = (base + j < n) ? in[base + j] : 0;
        vals[j] = s;
        s += v;
    }
    int ws = s;
#pragma unroll
    for (int o = 1; o < 32; o <<= 1) {
        int t = __shfl_up_sync(0xFFFFFFFFu, ws, o);
        if (lane >= o) ws += t;
    }
    if (lane == 31) wsum[wid] = ws;
    __syncthreads();
    if (wid == 0) {
        int w = wsum[lane];
#pragma unroll
        for (int o = 1; o < 32; o <<= 1) {
            int t = __shfl_up_sync(0xFFFFFFFFu, w, o);
            if (lane >= o) w += t;
        }
        wsum[lane] = w;
    }
    __syncthreads();
    int off = (wid ? wsum[wid - 1] : 0) + ws - s;
#pragma unroll
    for (int j = 0; j < CH; j++) {
        if (base + j <= n) out[base + j] = off + vals[j];
    }
}

__global__ void fill_csr(int E)
{
    int e = blockIdx.x * blockDim.x + threadIdx.x;
    if (e < E) {
        int r = g_ei32[e];
        int c = g_ei32[E + e];
        int p = atomicAdd(&g_fill[r], 1);
        g_adj_row[g_rowptr[r] + p] = c;
        int q = atomicAdd(&g_fill[NNODE + c], 1);
        g_adj_col[g_colptr[c] + q] = r;
    }
}

__global__ void finalize_deg(float* __restrict__ dinv, int n)
{
    int i = blockIdx.x * blockDim.x + threadIdx.x;
    if (i < n) dinv[i] = rsqrtf((float)g_deg[i] + 1.f);
}

// ---------------------------------------------------------------------------
// split kernels
// ---------------------------------------------------------------------------
// x -> fp16 (rounded) + bf16 hi/lo
__global__ void splitx(const float* __restrict__ s,
                       unsigned short* __restrict__ f16,
                       unsigned short* __restrict__ bh,
                       unsigned short* __restrict__ bl, int n4)
{
    int i = blockIdx.x * blockDim.x + threadIdx.x;
    if (i >= n4) return;
    float4 v = reinterpret_cast<const float4*>(s)[i];
    __half2* fp = reinterpret_cast<__half2*>(f16) + (size_t)i * 2;
    fp[0] = __halves2half2(__float2half_rn(v.x), __float2half_rn(v.y));
    fp[1] = __halves2half2(__float2half_rn(v.z), __float2half_rn(v.w));
    bf162* hp = reinterpret_cast<bf162*>(bh) + (size_t)i * 2;
    bf162* lp = reinterpret_cast<bf162*>(bl) + (size_t)i * 2;
    split2b(v.x, v.y, hp, lp);
    split2b(v.z, v.w, hp + 1, lp + 1);
}

// up to 4 equal-size matrices -> fp16 hi/lo planes
__global__ void splitw16(const float* __restrict__ s0, const float* __restrict__ s1,
                         const float* __restrict__ s2, const float* __restrict__ s3,
                         unsigned short* __restrict__ h, unsigned short* __restrict__ l,
                         int n4)
{
    const float* s = (blockIdx.y == 0) ? s0 : (blockIdx.y == 1) ? s1
                   : (blockIdx.y == 2) ? s2 : s3;
    long long ob = (long long)blockIdx.y * n4;
    int i = blockIdx.x * blockDim.x + threadIdx.x;
    if (i >= n4) return;
    float4 v = reinterpret_cast<const float4*>(s)[i];
    __half2* hp = reinterpret_cast<__half2*>(h) + (ob + i) * 2;
    __half2* lp = reinterpret_cast<__half2*>(l) + (ob + i) * 2;
    split2h(v.x, v.y, hp, lp);
    split2h(v.z, v.w, hp + 1, lp + 1);
}

// single matrix -> bf16 hi/lo planes
__global__ void splitwb(const float* __restrict__ s,
                        unsigned short* __restrict__ h, unsigned short* __restrict__ l,
                        int n4)
{
    int i = blockIdx.x * blockDim.x + threadIdx.x;
    if (i >= n4) return;
    float4 v = reinterpret_cast<const float4*>(s)[i];
    bf162* hp = reinterpret_cast<bf162*>(h) + (size_t)i * 2;
    bf162* lp = reinterpret_cast<bf162*>(l) + (size_t)i * 2;
    split2b(v.x, v.y, hp, lp);
    split2b(v.z, v.w, hp + 1, lp + 1);
}

// ---------------------------------------------------------------------------
// Gather kernels (atomic-free)
// ---------------------------------------------------------------------------
template<int F>
__global__ __launch_bounds__(256)
void gather_mean(const float* __restrict__ x, float* __restrict__ nb,
                 unsigned short* __restrict__ nbf16)
{
    constexpr int L = F / 4;
    constexpr int NPB = 256 / L;
    int node = blockIdx.x * NPB + threadIdx.x / L;
    int lane = threadIdx.x % L;
    if (node >= NNODE) return;

    int beg = g_rowptr[node], end = g_rowptr[node + 1];
    float4 s = make_float4(0.f, 0.f, 0.f, 0.f);
    for (int p = beg; p < end; ++p) {
        int j = g_adj_row[p];
        float4 v = __ldg(reinterpret_cast<const float4*>(x + (size_t)j * F) + lane);
        s.x += v.x; s.y += v.y; s.z += v.z; s.w += v.w;
    }
    int c = end - beg;
    float inv = (c > 0) ? 1.f / (float)c : 0.f;
    s.x *= inv; s.y *= inv; s.z *= inv; s.w *= inv;
    size_t q = (size_t)node * L + lane;
    reinterpret_cast<float4*>(nb)[q] = s;
    __half2* fp = reinterpret_cast<__half2*>(nbf16) + q * 2;
    fp[0] = __halves2half2(__float2half_rn(s.x), __float2half_rn(s.y));
    fp[1] = __halves2half2(__float2half_rn(s.z), __float2half_rn(s.w));
}

template<int F, bool ELU>
__global__ __launch_bounds__(256)
void gcn_fused(const float* __restrict__ h, const float* __restrict__ hs,
               const float* __restrict__ bias, const float* __restrict__ dinv,
               float* __restrict__ out,
               unsigned short* __restrict__ f16o,
               unsigned short* __restrict__ pbh, unsigned short* __restrict__ pbl)
{
    constexpr int L = F / 4;
    constexpr int NPB = 256 / L;
    int node = blockIdx.x * NPB + threadIdx.x / L;
    int lane = threadIdx.x % L;
    if (node >= NNODE) return;

    float di = dinv[node];
    int beg = g_colptr[node], end = g_colptr[node + 1];

    float4 hv = __ldg(reinterpret_cast<const float4*>(h + (size_t)node * F) + lane);
    float4 s = make_float4(di * hv.x, di * hv.y, di * hv.z, di * hv.w);

    for (int p = beg; p < end; ++p) {
        int j = g_adj_col[p];
        float dj = dinv[j];
        float4 v = __ldg(reinterpret_cast<const float4*>(h + (size_t)j * F) + lane);
        s.x += dj * v.x; s.y += dj * v.y; s.z += dj * v.z; s.w += dj * v.w;
    }

    float4 hsv = __ldg(reinterpret_cast<const float4*>(hs + (size_t)node * F) + lane);
    float4 bv  = __ldg(reinterpret_cast<const float4*>(bias) + lane);
    float rin = 1.f / ((float)g_cnt[node] + 1.f);

    float4 o;
    o.x = (di * s.x + bv.x + hsv.x) * rin;
    o.y = (di * s.y + bv.y + hsv.y) * rin;
    o.z = (di * s.z + bv.z + hsv.z) * rin;
    o.w = (di * s.w + bv.w + hsv.w) * rin;
    if (ELU) {
        o.x = o.x > 0.f ? o.x : (expf(o.x) - 1.f);
        o.y = o.y > 0.f ? o.y : (expf(o.y) - 1.f);
        o.z = o.z > 0.f ? o.z : (expf(o.z) - 1.f);
        o.w = o.w > 0.f ? o.w : (expf(o.w) - 1.f);
    }
    size_t q = (size_t)node * L + lane;
    reinterpret_cast<float4*>(out)[q] = o;
    if (f16o) {
        __half2* fp = reinterpret_cast<__half2*>(f16o) + q * 2;
        fp[0] = __halves2half2(__float2half_rn(o.x), __float2half_rn(o.y));
        fp[1] = __halves2half2(__float2half_rn(o.z), __float2half_rn(o.w));
        bf162* hp = reinterpret_cast<bf162*>(pbh) + q * 2;
        bf162* lp = reinterpret_cast<bf162*>(pbl) + q * 2;
        split2b(o.x, o.y, hp, lp);
        split2b(o.z, o.w, hp + 1, lp + 1);
    }
}

// ---------------------------------------------------------------------------
// relation elementwise over fused T = [tA | tB], emits fp32 + bf16 hi/lo
// ---------------------------------------------------------------------------
__device__ __forceinline__ float lrelu02(float v) { return v > 0.f ? v : 0.2f * v; }

__global__ void relation_ew(const float* __restrict__ x, const float* __restrict__ nb,
                            const float* __restrict__ T,
                            const float* __restrict__ m, float* __restrict__ out,
                            unsigned short* __restrict__ oh, unsigned short* __restrict__ ol,
                            int total4, int F4)
{
    int idx = blockIdx.x * blockDim.x + threadIdx.x;
    if (idx >= total4) return;
    int node = idx / F4, c = idx % F4;
    float4 xa = reinterpret_cast<const float4*>(x)[idx];
    float4 nv = reinterpret_cast<const float4*>(nb)[idx];
    float4 ta = reinterpret_cast<const float4*>(T)[(size_t)node * 2 * F4 + c];
    float4 tb = reinterpret_cast<const float4*>(T)[(size_t)node * 2 * F4 + F4 + c];
    float4 mv = reinterpret_cast<const float4*>(m)[c];

    float4 o;
    o.x = xa.x + (lrelu02(ta.x) + 1.f) * mv.x + lrelu02(tb.x) - nv.x;
    o.y = xa.y + (lrelu02(ta.y) + 1.f) * mv.y + lrelu02(tb.y) - nv.y;
    o.z = xa.z + (lrelu02(ta.z) + 1.f) * mv.z + lrelu02(tb.z) - nv.z;
    o.w = xa.w + (lrelu02(ta.w) + 1.f) * mv.w + lrelu02(tb.w) - nv.w;
    reinterpret_cast<float4*>(out)[idx] = o;

    bf162* hp = reinterpret_cast<bf162*>(oh) + (size_t)idx * 2;
    bf162* lp = reinterpret_cast<bf162*>(ol) + (size_t)idx * 2;
    split2b(o.x, o.y, hp, lp);
    split2b(o.z, o.w, hp + 1, lp + 1);
}

// ---------------------------------------------------------------------------
// fp16 2-term GEMM:  C[M,N] = sum_p A_p[M,K] @ (Bh_p + Bl_p)[N,K]^T
// A rounded fp16 (1 plane), B split fp16 hi/lo. 128 x BN_, BK=32, 256 thr.
// ---------------------------------------------------------------------------
#define SST 40

template<int BN_, int NPAIR>
__global__ __launch_bounds__(256)
void gemm_h2(const __half* __restrict__ A0, const __half* __restrict__ Bh0,
             const __half* __restrict__ Bl0,
             const __half* __restrict__ A1, const __half* __restrict__ Bh1,
             const __half* __restrict__ Bl1,
             float* __restrict__ C, int M, int N, int K)
{
    constexpr int NT  = BN_ / 32;
    constexpr int PA  = 128 * SST;
    constexpr int PB  = BN_ * SST;
    constexpr int STG = PA + 2 * PB;
    constexpr int TCH = 512 + BN_ * 8;
    constexpr int ITER = TCH / 256;

    extern __shared__ __half smh[];
    const int tid = threadIdx.x, wid = tid >> 5, lane = tid & 31;
    const int wm = wid & 1, wn = wid >> 1, grp = lane >> 2, tig = lane & 3;
    const int bm = blockIdx.y * 128, bn = blockIdx.x * BN_;

    const int KT = K / 32, TT = NPAIR * KT;

    float acc[4][NT][4];
#pragma unroll
    for (int mt = 0; mt < 4; mt++)
#pragma unroll
        for (int nt = 0; nt < NT; nt++)
#pragma unroll
            for (int q = 0; q < 4; q++) acc[mt][nt][q] = 0.f;

    auto issue = [&](int t) {
        __half* st = smh + (t & 1) * STG;
        int pair = (NPAIR == 2) ? (t / KT) : 0;
        int k0 = (t - pair * KT) * 32;
        const __half* A  = pair ? A1 : A0;
        const __half* Bh = pair ? Bh1 : Bh0;
        const __half* Bl = pair ? Bl1 : Bl0;
#pragma unroll
        for (int i = 0; i < ITER; i++) {
            int id = tid + i * 256;
            if (id < 512) {
                int row = id >> 2, ko = (id & 3) * 8;
                int gr = bm + row;
                int sz = (gr < M) ? 16 : 0;
                cpasync16(st + row * SST + ko,
                          A + (size_t)(gr < M ? gr : 0) * K + k0 + ko, sz);
            } else {
                int id2 = id - 512;
                int pl = id2 / (BN_ * 4), loc = id2 % (BN_ * 4);
                int row = loc >> 2, ko = (loc & 3) * 8;
                const __half* src = (pl ? Bl : Bh) + (size_t)(bn + row) * K + k0 + ko;
                cpasync16(st + PA + pl * PB + row * SST + ko, src, 16);
            }
        }
        cp_commit();
    };

    issue(0);
    for (int t = 0; t < TT; t++) {
        if (t + 1 < TT) {
            issue(t + 1);
            asm volatile("cp.async.wait_group 1;\n" ::: "memory");
        } else {
            asm volatile("cp.async.wait_group 0;\n" ::: "memory");
        }
        __syncthreads();

        const __half* st = smh + (t & 1) * STG;
        const __half* dBh = st + PA;
        const __half* dBl = st + PA + PB;

#pragma unroll
        for (int ks = 0; ks < 2; ks++) {
            const int kb = ks * 16;
            uint32_t a[4][4];
#pragma unroll
            for (int mt = 0; mt < 4; mt++) {
                int r0 = (wm * 64 + mt * 16 + grp) * SST + kb + 2 * tig;
                int r1 = r0 + 8 * SST;
                a[mt][0] = lds32(st, r0);     a[mt][1] = lds32(st, r1);
                a[mt][2] = lds32(st, r0 + 8); a[mt][3] = lds32(st, r1 + 8);
            }
            uint32_t bh[NT][2], bl[NT][2];
#pragma unroll
            for (int nt = 0; nt < NT; nt++) {
                int c0 = (wn * (BN_ / 4) + nt * 8 + grp) * SST + kb + 2 * tig;
                bh[nt][0] = lds32(dBh, c0); bh[nt][1] = lds32(dBh, c0 + 8);
                bl[nt][0] = lds32(dBl, c0); bl[nt][1] = lds32(dBl, c0 + 8);
            }
#pragma unroll
            for (int mt = 0; mt < 4; mt++)
#pragma unroll
                for (int nt = 0; nt < NT; nt++) {
                    mma_h(acc[mt][nt], a[mt], bh[nt]);
                    mma_h(acc[mt][nt], a[mt], bl[nt]);
                }
        }
        __syncthreads();
    }

#pragma unroll
    for (int mt = 0; mt < 4; mt++) {
        int row0 = bm + wm * 64 + mt * 16 + grp;
        int row1 = row0 + 8;
#pragma unroll
        for (int nt = 0; nt < NT; nt++) {
            int col = bn + wn * (BN_ / 4) + nt * 8 + 2 * tig;
            if (row0 < M)
                *reinterpret_cast<float2*>(C + (size_t)row0 * N + col) =
                    make_float2(acc[mt][nt][0], acc[mt][nt][1]);
            if (row1 < M)
                *reinterpret_cast<float2*>(C + (size_t)row1 * N + col) =
                    make_float2(acc[mt][nt][2], acc[mt][nt][3]);
        }
    }
}

// ---------------------------------------------------------------------------
// bf16 3-term dual-A GEMM:  C0 = (Ah0+Al0)@(Bh+Bl)^T, C1 = (Ah1+Al1)@(Bh+Bl)^T
// gridDim.y = 2*YB; blocks [0,YB) do (A0,C0), [YB,2YB) do (A1,C1).
// ---------------------------------------------------------------------------
template<int BN_>
__global__ __launch_bounds__(256)
void gemm_bf3(const bf16* __restrict__ Ah0, const bf16* __restrict__ Al0,
              const bf16* __restrict__ Ah1, const bf16* __restrict__ Al1,
              const bf16* __restrict__ Bh, const bf16* __restrict__ Bl,
              float* __restrict__ C0, float* __restrict__ C1,
              int M, int YB, int N, int K)
{
    constexpr int NT  = BN_ / 32;
    constexpr int PA  = 128 * SST;
    constexpr int PB  = BN_ * SST;
    constexpr int STG = 2 * PA + 2 * PB;
    constexpr int TCH = 1024 + BN_ * 8;
    constexpr int ITER = TCH / 256;

    extern __shared__ bf16 smb[];
    const int tid = threadIdx.x, wid = tid >> 5, lane = tid & 31;
    const int wm = wid & 1, wn = wid >> 1, grp = lane >> 2, tig = lane & 3;

    int by = blockIdx.y;
    const bf16* Ah = Ah0;
    const bf16* Al = Al0;
    float* C = C0;
    if (by >= YB) { by -= YB; Ah = Ah1; Al = Al1; C = C1; }
    const int bm = by * 128, bn = blockIdx.x * BN_;

    const int TT = K / 32;

    float acc[4][NT][4];
#pragma unroll
    for (int mt = 0; mt < 4; mt++)
#pragma unroll
        for (int nt = 0; nt < NT; nt++)
#pragma unroll
            for (int q = 0; q < 4; q++) acc[mt][nt][q] = 0.f;

    auto issue = [&](int t) {
        bf16* st = smb + (t & 1) * STG;
        int k0 = t * 32;
#pragma unroll
        for (int i = 0; i < ITER; i++) {
            int id = tid + i * 256;
            if (id < 1024) {
                int pl = id >> 9, loc = id & 511;
                int row = loc >> 2, ko = (loc & 3) * 8;
                int gr = bm + row;
                int sz = (gr < M) ? 16 : 0;
                const bf16* src = (pl ? Al : Ah) + (size_t)(gr < M ? gr : 0) * K + k0 + ko;
                cpasync16(st + pl * PA + row * SST + ko, src, sz);
            } else {
                int id2 = id - 1024;
                int pl = id2 / (BN_ * 4), loc = id2 % (BN_ * 4);
                int row = loc >> 2, ko = (loc & 3) * 8;
                const bf16* src = (pl ? Bl : Bh) + (size_t)(bn + row) * K + k0 + ko;
                cpasync16(st + 2 * PA + pl * PB + row * SST + ko, src, 16);
            }
        }
        cp_commit();
    };

    issue(0);
    for (int t = 0; t < TT; t++) {
        if (t + 1 < TT) {
            issue(t + 1);
            asm volatile("cp.async.wait_group 1;\n" ::: "memory");
        } else {
            asm volatile("cp.async.wait_group 0;\n" ::: "memory");
        }
        __syncthreads();

        const bf16* dAh = smb + (t & 1) * STG;
        const bf16* dAl = dAh + PA;
        const bf16* dBh = dAh + 2 * PA;
        const bf16* dBl = dBh + PB;

#pragma unroll
        for (int ks = 0; ks < 2; ks++) {
            const int kb = ks * 16;
            uint32_t ah[4][4], al[4][4];
#pragma unroll
            for (int mt = 0; mt < 4; mt++) {
                int r0 = (wm * 64 + mt * 16 + grp) * SST + kb + 2 * tig;
                int r1 = r0 + 8 * SST;
                ah[mt][0] = lds32(dAh, r0);     ah[mt][1] = lds32(dAh, r1);
                ah[mt][2] = lds32(dAh, r0 + 8); ah[mt][3] = lds32(dAh, r1 + 8);
                al[mt][0] = lds32(dAl, r0);     al[mt][1] = lds32(dAl, r1);
                al[mt][2] = lds32(dAl, r0 + 8); al[mt][3] = lds32(dAl, r1 + 8);
            }
            uint32_t bh[NT][2], bl[NT][2];
#pragma unroll
            for (int nt = 0; nt < NT; nt++) {
                int c0 = (wn * (BN_ / 4) + nt * 8 + grp) * SST + kb + 2 * tig;
                bh[nt][0] = lds32(dBh, c0); bh[nt][1] = lds32(dBh, c0 + 8);
                bl[nt][0] = lds32(dBl, c0); bl[nt][1] = lds32(dBl, c0 + 8);
            }
#pragma unroll
            for (int mt = 0; mt < 4; mt++)
#pragma unroll
                for (int nt = 0; nt < NT; nt++) {
                    mma_bf(acc[mt][nt], ah[mt], bh[nt]);
                    mma_bf(acc[mt][nt], ah[mt], bl[nt]);
                    mma_bf(acc[mt][nt], al[mt], bh[nt]);
                }
        }
        __syncthreads();
    }

#pragma unroll
    for (int mt = 0; mt < 4; mt++) {
        int row0 = bm + wm * 64 + mt * 16 + grp;
        int row1 = row0 + 8;
#pragma unroll
        for (int nt = 0; nt < NT; nt++) {
            int col = bn + wn * (BN_ / 4) + nt * 8 + 2 * tig;
            if (row0 < M)
                *reinterpret_cast<float2*>(C + (size_t)row0 * N + col) =
                    make_float2(acc[mt][nt][0], acc[mt][nt][1]);
            if (row1 < M)
                *reinterpret_cast<float2*>(C + (size_t)row1 * N + col) =
                    make_float2(acc[mt][nt][2], acc[mt][nt][3]);
        }
    }
}

// ---------------------------------------------------------------------------
// log_softmax over 64 columns; one warp per row
// ---------------------------------------------------------------------------
__global__ void logsoftmax64(const float* __restrict__ x, float* __restrict__ out, int n)
{
    int row = blockIdx.x * (blockDim.x >> 5) + (threadIdx.x >> 5);
    int lane = threadIdx.x & 31;
    if (row >= n) return;
    const float* xr = x + (size_t)row * 64;
    float a = xr[lane];
    float b = xr[lane + 32];
    float mx = fmaxf(a, b);
#pragma unroll
    for (int o = 16; o > 0; o >>= 1) mx = fmaxf(mx, __shfl_xor_sync(0xFFFFFFFFu, mx, o));
    float s = expf(a - mx) + expf(b - mx);
#pragma unroll
    for (int o = 16; o > 0; o >>= 1) s += __shfl_xor_sync(0xFFFFFFFFu, s, o);
    float lse = mx + logf(s);
    out[(size_t)row * 64 + lane] = a - lse;
    out[(size_t)row * 64 + lane + 32] = b - lse;
}

// ---------------------------------------------------------------------------
// Host launcher
// ---------------------------------------------------------------------------
#define SMH128  ((128 * SST + 2 * 128 * SST) * 2 * 2)            // 61440
#define SMB128  ((2 * 128 * SST + 2 * 128 * SST) * 2 * 2)        // 81920
#define SMB64   ((2 * 128 * SST + 2 * 64 * SST) * 2 * 2)         // 61440

extern "C" void kernel_launch(void* const* d_in, const int* in_sizes, int n_in,
                              void* d_out, int out_size)
{
    const float* x      = (const float*)d_in[0];
    const int*   ei_raw = (const int*)d_in[1];
    const float* r1_g1 = (const float*)d_in[3];
    const float* r1_g2 = (const float*)d_in[4];
    const float* r1_b1 = (const float*)d_in[5];
    const float* r1_b2 = (const float*)d_in[6];
    const float* r1_m  = (const float*)d_in[7];
    const float* gc1_w = (const float*)d_in[8];
    const float* gc1_b = (const float*)d_in[9];
    const float* r2_g1 = (const float*)d_in[10];
    const float* r2_g2 = (const float*)d_in[11];
    const float* r2_b1 = (const float*)d_in[12];
    const float* r2_b2 = (const float*)d_in[13];
    const float* r2_m  = (const float*)d_in[14];
    const float* gc2_w = (const float*)d_in[15];
    const float* gc2_b = (const float*)d_in[16];

    float* out = (float*)d_out;
    float* o_x2  = out;
    float* o_lsm = out + (long long)NNODE * NCLASS;
    float* o_o1  = out + 2ll * NNODE * NCLASS;
    float* o_o2  = o_o1 + (long long)NNODE * NFEAT;

    float* S = nullptr;        cudaGetSymbolAddress((void**)&S, g_scratch);
    unsigned* flag = nullptr;  cudaGetSymbolAddress((void**)&flag, g_idx_is32);
    int* cntp = nullptr;       cudaGetSymbolAddress((void**)&cntp, g_cnt);
    int* degp = nullptr;       cudaGetSymbolAddress((void**)&degp, g_deg);
    int* fillp = nullptr;      cudaGetSymbolAddress((void**)&fillp, g_fill);

    unsigned short *xf16, *nbf16, *x1f16, *xbh, *xbl, *obh, *obl, *x1bh, *x1bl;
    unsigned short *w16h, *w16l, *wbh, *wbl;
    cudaGetSymbolAddress((void**)&xf16, g_xf16);
    cudaGetSymbolAddress((void**)&nbf16, g_nbf16);
    cudaGetSymbolAddress((void**)&x1f16, g_x1f16);
    cudaGetSymbolAddress((void**)&xbh, g_xbh);   cudaGetSymbolAddress((void**)&xbl, g_xbl);
    cudaGetSymbolAddress((void**)&obh, g_obh);   cudaGetSymbolAddress((void**)&obl, g_obl);
    cudaGetSymbolAddress((void**)&x1bh, g_x1bh); cudaGetSymbolAddress((void**)&x1bl, g_x1bl);
    cudaGetSymbolAddress((void**)&w16h, g_w16h); cudaGetSymbolAddress((void**)&w16l, g_w16l);
    cudaGetSymbolAddress((void**)&wbh, g_wbh);   cudaGetSymbolAddress((void**)&wbl, g_wbl);

    float* nb1  = S + OFF_NB1;
    float* tT1  = S + OFF_TA1;   // fused [N,1024]
    float* h1   = S + OFF_H1;
    float* hs1  = S + OFF_HS1;
    float* x1   = S + OFF_X1;
    float* nb2  = S + OFF_NB2;
    float* tT2  = S + OFF_TA2;   // fused [N,512]
    float* h2   = S + OFF_H2;
    float* hs2  = S + OFF_HS2;
    float* dinv = S + OFF_DINV;

    const int N = NNODE, E = NEDGE;

    cudaFuncSetAttribute(gemm_h2<128, 2>, cudaFuncAttributeMaxDynamicSharedMemorySize, SMH128);
    cudaFuncSetAttribute(gemm_bf3<128>,   cudaFuncAttributeMaxDynamicSharedMemorySize, SMB128);
    cudaFuncSetAttribute(gemm_bf3<64>,    cudaFuncAttributeMaxDynamicSharedMemorySize, SMB64);

    cudaMemsetAsync(cntp, 0, N * sizeof(int));
    cudaMemsetAsync(degp, 0, N * sizeof(int));
    cudaMemsetAsync(fillp, 0, 2 * N * sizeof(int));
    cudaMemsetAsync(flag, 0, sizeof(unsigned));

    detect_idx<<<(E + 255) / 256, 256>>>(ei_raw);
    convert_idx<<<(2 * E + 255) / 256, 256>>>(ei_raw);

    count_int<<<(E + 255) / 256, 256>>>(E);
    scan2<<<2, 1024>>>();
    finalize_deg<<<(N + 255) / 256, 256>>>(dinv, N);
    fill_csr<<<(E + 255) / 256, 256>>>(E);

    // splits
    splitx<<<(N * NFEAT / 4 + 255) / 256, 256>>>(x, xf16, xbh, xbl, N * NFEAT / 4);
    // relation weights (fp16 h/l): layer1 [g1;b1][g2;b2], layer2 same
    splitw16<<<dim3((65536 + 255) / 256, 4), 256>>>(r1_g1, r1_b1, r1_g2, r1_b2,
                                                    w16h + W16_1A, w16l + W16_1A, 65536);
    splitw16<<<dim3((16384 + 255) / 256, 4), 256>>>(r2_g1, r2_b1, r2_g2, r2_b2,
                                                    w16h + W16_2A, w16l + W16_2A, 16384);
    // gc weights (bf16 h/l)
    splitwb<<<(32768 + 255) / 256, 256>>>(gc1_w, wbh + WB_GC1, wbl + WB_GC1, 32768);
    splitwb<<<(4096 + 255) / 256, 256>>>(gc2_w, wbh + WB_GC2, wbl + WB_GC2, 4096);

    const __half* hxf  = (const __half*)xf16;
    const __half* hnbf = (const __half*)nbf16;
    const __half* hx1f = (const __half*)x1f16;
    const __half* hw16h = (const __half*)w16h;
    const __half* hw16l = (const __half*)w16l;
    const bf16* bxh = (const bf16*)xbh, *bxl = (const bf16*)xbl;
    const bf16* boh = (const bf16*)obh, *bol = (const bf16*)obl;
    const bf16* b1h = (const bf16*)x1bh, *b1l = (const bf16*)x1bl;
    const bf16* bwh = (const bf16*)wbh,  *bwl = (const bf16*)wbl;

    // ---------------- Layer 1 ----------------
    gather_mean<NFEAT><<<(N * (NFEAT / 4) + 255) / 256, 256>>>(x, nb1, nbf16);

    // fused relation GEMM: T1 = [x|nb] @ fused-weights, N=1024, fp16 2-term
    gemm_h2<128, 2><<<dim3(8, 157), 256, SMH128>>>(
        hxf,  hw16h + W16_1A, hw16l + W16_1A,
        hnbf, hw16h + W16_1B, hw16l + W16_1B,
        tT1, N, 1024, NFEAT);
    relation_ew<<<(N * (NFEAT / 4) + 255) / 256, 256>>>(x, nb1, tT1, r1_m,
                                                        o_o1, obh, obl,
                                                        N * (NFEAT / 4), NFEAT / 4);
    // gc1: h1 = x@W^T, hs1 = o1@W^T — dual-M single launch, bf16 3-term
    gemm_bf3<128><<<dim3(2, 314), 256, SMB128>>>(
        bxh, bxl, boh, bol, bwh + WB_GC1, bwl + WB_GC1,
        h1, hs1, N, 157, NHID, NFEAT);
    gcn_fused<NHID, true><<<(N * (NHID / 4) + 255) / 256, 256>>>(
        h1, hs1, gc1_b, dinv, x1, x1f16, x1bh, x1bl);

    // ---------------- Layer 2 ----------------
    gather_mean<NHID><<<(N * (NHID / 4) + 255) / 256, 256>>>(x1, nb2, nbf16);

    gemm_h2<128, 2><<<dim3(4, 157), 256, SMH128>>>(
        hx1f, hw16h + W16_2A, hw16l + W16_2A,
        hnbf, hw16h + W16_2B, hw16l + W16_2B,
        tT2, N, 512, NHID);
    relation_ew<<<(N * (NHID / 4) + 255) / 256, 256>>>(x1, nb2, tT2, r2_m,
                                                       o_o2, obh, obl,
                                                       N * (NHID / 4), NHID / 4);
    gemm_bf3<64><<<dim3(1, 314), 256, SMB64>>>(
        b1h, b1l, boh, bol, bwh + WB_GC2, bwl + WB_GC2,
        h2, hs2, N, 157, NCLASS, NHID);
    gcn_fused<NCLASS, false><<<(N * (NCLASS / 4) + 255) / 256, 256>>>(
        h2, hs2, gc2_b, dinv, o_x2, nullptr, nullptr, nullptr);

    logsoftmax64<<<(N * 32 + 255) / 256, 256>>>(o_x2, o_lsm, N);
}